// round 3
// baseline (speedup 1.0000x reference)
#include <cuda_runtime.h>
#include <cstdint>
#include <math.h>

#define B_    64
#define N_    20000
#define F1_   512
#define F2_   256
#define D_    128
#define KSEL_ 20

// ---------------- static device scratch (no allocations allowed) ----------------
__device__ float g_V[N_ * D_];       // V = ge@Wv + bv
__device__ float g_kpb[N_ * D_];     // Km@W1[D:] + b1
__device__ float g_Q[B_ * D_];       // Q = pe@Wq + bq
__device__ float g_qp[B_ * D_];      // Q@W1[:D]
__device__ float g_m[B_ * N_];       // logits = sim / TEMP
__device__ float g_mmax[B_];         // per-b max of logits (for argmax pruning)
__device__ int   g_sel[B_ * KSEL_];  // argmax indices

// ---------------- K1: Q and q_part ----------------
__global__ __launch_bounds__(128) void k_qprep(const float* __restrict__ pe,
                                               const float* __restrict__ Wq,
                                               const float* __restrict__ bq,
                                               const float* __restrict__ W1) {
    __shared__ float pes[F1_];
    __shared__ float Qs[D_];
    const int b = blockIdx.x, d = threadIdx.x;
    for (int i = d; i < F1_; i += 128) pes[i] = pe[b * F1_ + i];
    __syncthreads();
    float acc = bq[d];
    #pragma unroll 4
    for (int f = 0; f < F1_; f++) acc = fmaf(pes[f], Wq[f * D_ + d], acc);
    g_Q[b * D_ + d] = acc;
    Qs[d] = acc;
    __syncthreads();
    float a2 = 0.f;
    #pragma unroll 4
    for (int j = 0; j < D_; j++) a2 = fmaf(Qs[j], W1[j * D_ + d], a2);
    g_qp[b * D_ + d] = a2;
}

// ---------------- K2: gene GEMMs (Km, V, kpb) ----------------
__global__ __launch_bounds__(128) void k_gene(const float* __restrict__ ge,
                                              const float* __restrict__ Wk,
                                              const float* __restrict__ bk,
                                              const float* __restrict__ Wv,
                                              const float* __restrict__ bv,
                                              const float* __restrict__ W1,
                                              const float* __restrict__ b1) {
    __shared__ __align__(16) float ges[16][256];
    __shared__ __align__(16) float kms[16][132];
    const int d = threadIdx.x;
    const int n0 = blockIdx.x * 16;

    // stage gene tile [16 x 256] via float4
    const float4* ge4 = (const float4*)(ge + n0 * F2_);
    for (int i = d; i < 16 * 64; i += 128) {
        int r = i >> 6, c = i & 63;
        float4 v = ge4[r * 64 + c];
        *(float4*)&ges[r][c * 4] = v;
    }
    __syncthreads();

    float ak[16], av[16];
    const float bkd = bk[d], bvd = bv[d];
    #pragma unroll
    for (int r = 0; r < 16; r++) { ak[r] = bkd; av[r] = bvd; }

    for (int f4 = 0; f4 < 64; f4++) {
        const int f = f4 * 4;
        float wk0 = Wk[(f+0)*D_ + d], wk1 = Wk[(f+1)*D_ + d];
        float wk2 = Wk[(f+2)*D_ + d], wk3 = Wk[(f+3)*D_ + d];
        float wv0 = Wv[(f+0)*D_ + d], wv1 = Wv[(f+1)*D_ + d];
        float wv2 = Wv[(f+2)*D_ + d], wv3 = Wv[(f+3)*D_ + d];
        #pragma unroll
        for (int r = 0; r < 16; r++) {
            float4 x = *(const float4*)&ges[r][f];
            ak[r] = fmaf(x.x, wk0, ak[r]); ak[r] = fmaf(x.y, wk1, ak[r]);
            ak[r] = fmaf(x.z, wk2, ak[r]); ak[r] = fmaf(x.w, wk3, ak[r]);
            av[r] = fmaf(x.x, wv0, av[r]); av[r] = fmaf(x.y, wv1, av[r]);
            av[r] = fmaf(x.z, wv2, av[r]); av[r] = fmaf(x.w, wv3, av[r]);
        }
    }

    // stash Km tile to smem, write V out
    #pragma unroll
    for (int r = 0; r < 16; r++) kms[r][d] = ak[r];
    #pragma unroll
    for (int r = 0; r < 16; r++) g_V[(n0 + r) * D_ + d] = av[r];
    __syncthreads();

    // stage 2: kpb = Km @ W1[D:] + b1
    float a2[16];
    const float b1d = b1[d];
    #pragma unroll
    for (int r = 0; r < 16; r++) a2[r] = b1d;
    const float* W1p = W1 + D_ * D_;
    for (int j4 = 0; j4 < 32; j4++) {
        const int j = j4 * 4;
        float w0 = W1p[(j+0)*D_ + d], w1 = W1p[(j+1)*D_ + d];
        float w2_ = W1p[(j+2)*D_ + d], w3 = W1p[(j+3)*D_ + d];
        #pragma unroll
        for (int r = 0; r < 16; r++) {
            float4 k4 = *(const float4*)&kms[r][j];
            a2[r] = fmaf(k4.x, w0, a2[r]); a2[r] = fmaf(k4.y, w1, a2[r]);
            a2[r] = fmaf(k4.z, w2_, a2[r]); a2[r] = fmaf(k4.w, w3, a2[r]);
        }
    }
    #pragma unroll
    for (int r = 0; r < 16; r++) g_kpb[(n0 + r) * D_ + d] = a2[r];
}

// ---------------- K3: logits m[b,n] ----------------
// block = 128 threads (4 warps); warp handles 32 n (lane = n), 32 b's in registers.
__global__ __launch_bounds__(128) void k_logits(const float* __restrict__ w2,
                                                const float* __restrict__ b2p) {
    __shared__ float4 qps[32][32];   // [b_local][d4]
    __shared__ float4 ws[32];
    const int tid = threadIdx.x;
    const int lane = tid & 31, w = tid >> 5;
    const int b0 = blockIdx.y * 32;

    const float4* qp4 = (const float4*)(g_qp + b0 * D_);
    for (int i = tid; i < 32 * 32; i += 128) ((float4*)qps)[i] = qp4[i];
    if (tid < 32) ws[tid] = ((const float4*)w2)[tid];
    __syncthreads();

    const int n = blockIdx.x * 128 + w * 32 + lane;
    const int nc = n < N_ ? n : N_ - 1;
    const float4* kp4 = (const float4*)(g_kpb + nc * D_);

    float acc[32];
    #pragma unroll
    for (int b = 0; b < 32; b++) acc[b] = 0.f;

    #pragma unroll 2
    for (int d4 = 0; d4 < 32; d4++) {
        float4 k4 = kp4[d4];
        float4 w4 = ws[d4];
        #pragma unroll
        for (int b = 0; b < 32; b++) {
            float4 q4 = qps[b][d4];
            float x;
            x = q4.x + k4.x; acc[b] = fmaf(fmaxf(x, 0.1f * x), w4.x, acc[b]);
            x = q4.y + k4.y; acc[b] = fmaf(fmaxf(x, 0.1f * x), w4.y, acc[b]);
            x = q4.z + k4.z; acc[b] = fmaf(fmaxf(x, 0.1f * x), w4.z, acc[b]);
            x = q4.w + k4.w; acc[b] = fmaf(fmaxf(x, 0.1f * x), w4.w, acc[b]);
        }
    }
    if (n < N_) {
        const float b2 = *b2p;
        #pragma unroll
        for (int b = 0; b < 32; b++)
            g_m[(b0 + b) * N_ + n] = (acc[b] + b2) * 2.0f;   // /TEMP, TEMP=0.5
    }
}

// ---------------- K3b: per-b max of logits ----------------
__global__ __launch_bounds__(256) void k_mmax() {
    __shared__ float red[256];
    const int b = blockIdx.x;
    float mx = -1e30f;
    for (int n = threadIdx.x; n < N_; n += 256) mx = fmaxf(mx, g_m[b * N_ + n]);
    red[threadIdx.x] = mx;
    __syncthreads();
    for (int s = 128; s > 0; s >>= 1) {
        if (threadIdx.x < s) red[threadIdx.x] = fmaxf(red[threadIdx.x], red[threadIdx.x + s]);
        __syncthreads();
    }
    if (threadIdx.x == 0) g_mmax[b] = red[0];
}

// ---------------- K4: gumbel argmax (threefry2x32, partitionable) ----------------
#define TFR(r) { x0 += x1; x1 = __funnelshift_l(x1, x1, (r)); x1 ^= x0; }

__device__ __forceinline__ unsigned threefry_bits(unsigned idx) {
    const unsigned ks1 = 42u, ks2 = 0x1BD11BF0u;   // ks0 = 0
    unsigned x0 = 0u;            // x0 += ks0
    unsigned x1 = idx + ks1;     // x1 += ks1
    TFR(13) TFR(15) TFR(26) TFR(6);  x0 += ks1; x1 += ks2 + 1u;
    TFR(17) TFR(29) TFR(16) TFR(24); x0 += ks2; x1 += 0u  + 2u;
    TFR(13) TFR(15) TFR(26) TFR(6);  x0 += 0u;  x1 += ks1 + 3u;
    TFR(17) TFR(29) TFR(16) TFR(24); x0 += ks1; x1 += ks2 + 4u;
    TFR(13) TFR(15) TFR(26) TFR(6);  x0 += ks2; x1 += 0u  + 5u;
    return x0 ^ x1;   // 32-bit partitionable output
}

__device__ __forceinline__ unsigned enc_f(float z) {
    unsigned u = __float_as_uint(z);
    return (u & 0x80000000u) ? ~u : (u | 0x80000000u);
}
__device__ __forceinline__ float dec_f(unsigned e) {
    unsigned u = (e & 0x80000000u) ? (e & 0x7fffffffu) : ~e;
    return __uint_as_float(u);
}

__global__ __launch_bounds__(256) void k_argmax() {
    const int row = blockIdx.x;            // b*KSEL + k
    const int b = row / KSEL_;
    const float* mrow = g_m + b * N_;
    const float mmax = g_mmax[b];
    __shared__ unsigned sbest;
    __shared__ float szred[256];
    __shared__ int   sired[256];
    const int tid = threadIdx.x;
    if (tid == 0) sbest = 0u;              // dec(0) = NaN -> no prune in iter 0
    __syncthreads();

    const unsigned base = (unsigned)row * (unsigned)N_;
    float lbest = -1e30f;
    int   libest = 0x7fffffff;

    for (int j = 0; j < 79; j++) {
        unsigned e = *(volatile unsigned*)&sbest;
        float t = dec_f(e) - mmax;
        float uth = expf(-expf(-t)) - 2e-6f;   // conservative (NaN-safe: compare fails)
        int n = j * 256 + tid;
        if (n < N_) {
            unsigned bits = threefry_bits(base + (unsigned)n);
            float f = __uint_as_float((bits >> 9) | 0x3f800000u) - 1.0f;
            float u = fmaxf(f, 1.17549435e-38f);
            if (!(u <= uth)) {
                float g = -logf(-logf(u));
                float z = mrow[n] + g;
                if (z > lbest || (z == lbest && n < libest)) {
                    lbest = z; libest = n;
                    atomicMax(&sbest, enc_f(z));
                }
            }
        }
    }
    szred[tid] = lbest; sired[tid] = libest;
    __syncthreads();
    for (int s = 128; s > 0; s >>= 1) {
        if (tid < s) {
            float oz = szred[tid + s]; int oi = sired[tid + s];
            if (oz > szred[tid] || (oz == szred[tid] && oi < sired[tid])) {
                szred[tid] = oz; sired[tid] = oi;
            }
        }
        __syncthreads();
    }
    if (tid == 0) g_sel[row] = sired[0];
}

// ---------------- K5: gather + scores + softmax + context ----------------
__global__ __launch_bounds__(128) void k_context(float* __restrict__ out) {
    const int b = blockIdx.x, d = threadIdx.x;
    const int lane = d & 31, w = d >> 5;
    __shared__ int ssel[KSEL_];
    __shared__ float part[4][KSEL_];
    __shared__ float ssc[KSEL_];
    if (d < KSEL_) ssel[d] = g_sel[b * KSEL_ + d];
    __syncthreads();
    const float q = g_Q[b * D_ + d];
    float v[KSEL_];
    #pragma unroll
    for (int k = 0; k < KSEL_; k++) v[k] = g_V[ssel[k] * D_ + d];
    #pragma unroll
    for (int k = 0; k < KSEL_; k++) {
        float p = q * v[k];
        p += __shfl_down_sync(0xffffffffu, p, 16);
        p += __shfl_down_sync(0xffffffffu, p, 8);
        p += __shfl_down_sync(0xffffffffu, p, 4);
        p += __shfl_down_sync(0xffffffffu, p, 2);
        p += __shfl_down_sync(0xffffffffu, p, 1);
        if (lane == 0) part[w][k] = p;
    }
    __syncthreads();
    if (d < KSEL_)
        ssc[d] = (part[0][d] + part[1][d] + part[2][d] + part[3][d]) / sqrtf(128.0f);
    __syncthreads();
    float mx = -1e30f;
    #pragma unroll
    for (int k = 0; k < KSEL_; k++) mx = fmaxf(mx, ssc[k]);
    float e[KSEL_], sum = 0.f;
    #pragma unroll
    for (int k = 0; k < KSEL_; k++) { e[k] = expf(ssc[k] - mx); sum += e[k]; }
    const float inv = 1.0f / sum;
    float ctx = 0.f;
    #pragma unroll
    for (int k = 0; k < KSEL_; k++) ctx = fmaf(e[k] * inv, v[k], ctx);
    out[b * D_ + d] = ctx;
}

// ---------------- launch ----------------
extern "C" void kernel_launch(void* const* d_in, const int* in_sizes, int n_in,
                              void* d_out, int out_size) {
    const float* pe = (const float*)d_in[0];
    const float* ge = (const float*)d_in[1];
    const float* Wq = (const float*)d_in[2];
    const float* bq = (const float*)d_in[3];
    const float* Wk = (const float*)d_in[4];
    const float* bk = (const float*)d_in[5];
    const float* Wv = (const float*)d_in[6];
    const float* bv = (const float*)d_in[7];
    const float* W1 = (const float*)d_in[8];
    const float* b1 = (const float*)d_in[9];
    const float* w2 = (const float*)d_in[10];
    const float* b2 = (const float*)d_in[11];

    k_qprep<<<B_, 128>>>(pe, Wq, bq, W1);
    k_gene<<<N_ / 16, 128>>>(ge, Wk, bk, Wv, bv, W1, b1);
    k_logits<<<dim3((N_ + 127) / 128, 2), 128>>>(w2, b2);
    k_mmax<<<B_, 256>>>();
    k_argmax<<<B_ * KSEL_, 256>>>();
    k_context<<<B_, 128>>>((float*)d_out);
}

// round 4
// speedup vs baseline: 1.0568x; 1.0568x over previous
#include <cuda_runtime.h>
#include <cstdint>
#include <math.h>

#define B_    64
#define N_    20000
#define F1_   512
#define F2_   256
#define D_    128
#define KSEL_ 20

typedef unsigned long long u64t;

// ---------------- static device scratch (no allocations allowed) ----------------
__device__ float    g_V[N_ * D_];        // V = ge@Wv + bv
__device__ float    g_kpb[N_ * D_];      // Km@W1[D:] + b1
__device__ float    g_Q[B_ * D_];        // Q = pe@Wq + bq
__device__ float    g_qp2f[D_ * B_];     // q_part, packed layout [d][b]
__device__ float    g_m[B_ * N_];        // logits = sim / TEMP
__device__ unsigned g_mmax_bits[B_];     // per-b max of logits, enc_f encoded
__device__ int      g_sel[B_ * KSEL_];   // argmax indices

// ---------------- f32x2 packed helpers (sm_103a) ----------------
__device__ __forceinline__ u64t pack2(float lo, float hi) {
    u64t r; asm("mov.b64 %0,{%1,%2};" : "=l"(r) : "f"(lo), "f"(hi)); return r;
}
__device__ __forceinline__ float2 unpack2(u64t v) {
    float2 r; asm("mov.b64 {%0,%1},%2;" : "=f"(r.x), "=f"(r.y) : "l"(v)); return r;
}
__device__ __forceinline__ u64t add2(u64t a, u64t b) {
    u64t r; asm("add.rn.f32x2 %0,%1,%2;" : "=l"(r) : "l"(a), "l"(b)); return r;
}
__device__ __forceinline__ u64t fma2(u64t a, u64t b, u64t c) {
    u64t r; asm("fma.rn.f32x2 %0,%1,%2,%3;" : "=l"(r) : "l"(a), "l"(b), "l"(c)); return r;
}
__device__ __forceinline__ u64t abs2(u64t a) { return a & 0x7FFFFFFF7FFFFFFFULL; }

// float -> monotone unsigned (for atomicMax over signed floats)
__device__ __forceinline__ unsigned enc_f(float z) {
    unsigned u = __float_as_uint(z);
    return (u & 0x80000000u) ? ~u : (u | 0x80000000u);
}
__device__ __forceinline__ float dec_f(unsigned e) {
    unsigned u = (e & 0x80000000u) ? (e & 0x7fffffffu) : ~e;
    return __uint_as_float(u);
}

// ---------------- K1: Q, q_part (packed layout), mmax init ----------------
__global__ __launch_bounds__(128) void k_qprep(const float* __restrict__ pe,
                                               const float* __restrict__ Wq,
                                               const float* __restrict__ bq,
                                               const float* __restrict__ W1) {
    __shared__ float pes[F1_];
    __shared__ float Qs[D_];
    const int b = blockIdx.x, d = threadIdx.x;
    if (d == 0) g_mmax_bits[b] = 0u;           // reset per launch (graph replay safe)
    for (int i = d; i < F1_; i += 128) pes[i] = pe[b * F1_ + i];
    __syncthreads();
    float acc = bq[d];
    #pragma unroll 4
    for (int f = 0; f < F1_; f++) acc = fmaf(pes[f], Wq[f * D_ + d], acc);
    g_Q[b * D_ + d] = acc;
    Qs[d] = acc;
    __syncthreads();
    float a2 = 0.f;
    #pragma unroll 4
    for (int j = 0; j < D_; j++) a2 = fmaf(Qs[j], W1[j * D_ + d], a2);
    g_qp2f[d * B_ + b] = a2;                   // [d][b] packed layout for k_logits
}

// ---------------- K2: gene GEMMs (Km, V, kpb) with f32x2 ----------------
// 64 threads; thread owns d-pair (2*tid, 2*tid+1); 16 gene rows per block.
__global__ __launch_bounds__(64) void k_gene(const float* __restrict__ ge,
                                             const float* __restrict__ Wk,
                                             const float* __restrict__ bk,
                                             const float* __restrict__ Wv,
                                             const float* __restrict__ bv,
                                             const float* __restrict__ W1,
                                             const float* __restrict__ b1) {
    __shared__ __align__(16) float ges[16][256];
    __shared__ __align__(16) float kms[16][132];
    const int d2 = threadIdx.x;                // 0..63
    const int n0 = blockIdx.x * 16;

    // stage gene tile [16 x 256] via float4
    const float4* ge4 = (const float4*)(ge + n0 * F2_);
    for (int i = d2; i < 16 * 64; i += 64) {
        int r = i >> 6, c = i & 63;
        *(float4*)&ges[r][c * 4] = ge4[r * 64 + c];
    }
    __syncthreads();

    const float2* Wk2 = (const float2*)Wk;
    const float2* Wv2 = (const float2*)Wv;

    float2 bkv = ((const float2*)bk)[d2];
    float2 bvv = ((const float2*)bv)[d2];
    u64t bk2 = pack2(bkv.x, bkv.y), bv2 = pack2(bvv.x, bvv.y);

    u64t ak2[16], av2[16];
    #pragma unroll
    for (int r = 0; r < 16; r++) { ak2[r] = bk2; av2[r] = bv2; }

    for (int f4 = 0; f4 < 64; f4++) {
        const int f = f4 * 4;
        float2 a0 = Wk2[(f+0)*64 + d2], a1 = Wk2[(f+1)*64 + d2];
        float2 a2_ = Wk2[(f+2)*64 + d2], a3 = Wk2[(f+3)*64 + d2];
        float2 v0 = Wv2[(f+0)*64 + d2], v1 = Wv2[(f+1)*64 + d2];
        float2 v2_ = Wv2[(f+2)*64 + d2], v3 = Wv2[(f+3)*64 + d2];
        u64t wk0 = pack2(a0.x,a0.y), wk1 = pack2(a1.x,a1.y);
        u64t wk2_ = pack2(a2_.x,a2_.y), wk3 = pack2(a3.x,a3.y);
        u64t wv0 = pack2(v0.x,v0.y), wv1 = pack2(v1.x,v1.y);
        u64t wv2_ = pack2(v2_.x,v2_.y), wv3 = pack2(v3.x,v3.y);
        #pragma unroll
        for (int r = 0; r < 16; r++) {
            float4 x = *(const float4*)&ges[r][f];
            u64t xx;
            xx = pack2(x.x, x.x); ak2[r] = fma2(xx, wk0, ak2[r]); av2[r] = fma2(xx, wv0, av2[r]);
            xx = pack2(x.y, x.y); ak2[r] = fma2(xx, wk1, ak2[r]); av2[r] = fma2(xx, wv1, av2[r]);
            xx = pack2(x.z, x.z); ak2[r] = fma2(xx, wk2_, ak2[r]); av2[r] = fma2(xx, wv2_, av2[r]);
            xx = pack2(x.w, x.w); ak2[r] = fma2(xx, wk3, ak2[r]); av2[r] = fma2(xx, wv3, av2[r]);
        }
    }

    // stash Km to smem; write V out (64-bit stores, lo = even d)
    #pragma unroll
    for (int r = 0; r < 16; r++) *(u64t*)&kms[r][2 * d2] = ak2[r];
    #pragma unroll
    for (int r = 0; r < 16; r++) *(u64t*)&g_V[(n0 + r) * D_ + 2 * d2] = av2[r];
    __syncthreads();

    // stage 2: kpb = Km @ W1[D:] + b1
    const float2* W1p2 = (const float2*)(W1 + D_ * D_);
    float2 b1v = ((const float2*)b1)[d2];
    u64t b1p = pack2(b1v.x, b1v.y);
    u64t c2[16];
    #pragma unroll
    for (int r = 0; r < 16; r++) c2[r] = b1p;

    for (int j4 = 0; j4 < 32; j4++) {
        const int j = j4 * 4;
        float2 w0 = W1p2[(j+0)*64 + d2], w1 = W1p2[(j+1)*64 + d2];
        float2 w2_ = W1p2[(j+2)*64 + d2], w3 = W1p2[(j+3)*64 + d2];
        u64t p0 = pack2(w0.x,w0.y), p1 = pack2(w1.x,w1.y);
        u64t p2 = pack2(w2_.x,w2_.y), p3 = pack2(w3.x,w3.y);
        #pragma unroll
        for (int r = 0; r < 16; r++) {
            float4 k4 = *(const float4*)&kms[r][j];
            u64t xx;
            xx = pack2(k4.x, k4.x); c2[r] = fma2(xx, p0, c2[r]);
            xx = pack2(k4.y, k4.y); c2[r] = fma2(xx, p1, c2[r]);
            xx = pack2(k4.z, k4.z); c2[r] = fma2(xx, p2, c2[r]);
            xx = pack2(k4.w, k4.w); c2[r] = fma2(xx, p3, c2[r]);
        }
    }
    #pragma unroll
    for (int r = 0; r < 16; r++) *(u64t*)&g_kpb[(n0 + r) * D_ + 2 * d2] = c2[r];
}

// ---------------- K3: logits m[b,n] with f32x2, fused per-b max ----------------
// 128 threads, thread = one n; 32 b per block (16 b-pairs in packed accumulators).
// lrelu(x) = 0.55x + 0.45|x|  ->  w*lrelu(x) = (0.55w)x + (0.45w)|x|
__global__ __launch_bounds__(128) void k_logits(const float* __restrict__ w2,
                                                const float* __restrict__ b2p) {
    __shared__ __align__(16) float spq[D_][32];   // [d][b_local]
    __shared__ float4 ws[32];
    const int tid = threadIdx.x;
    const int lane = tid & 31;
    const int b0 = blockIdx.y * 32;

    for (int i = tid; i < 1024; i += 128) {       // 128 d x 32 b = 1024 float4s /4
        int d = i >> 3, c = i & 7;
        *(float4*)&spq[d][4 * c] = *(const float4*)&g_qp2f[d * B_ + b0 + 4 * c];
    }
    if (tid < 32) ws[tid] = ((const float4*)w2)[tid];
    __syncthreads();

    const int n = blockIdx.x * 128 + tid;
    const int nc = n < N_ ? n : N_ - 1;
    const float4* kp4 = (const float4*)(g_kpb + nc * D_);

    u64t acc2[16];
    #pragma unroll
    for (int p = 0; p < 16; p++) acc2[p] = 0ull;

    for (int d4 = 0; d4 < 32; d4++) {
        float4 k4 = kp4[d4];
        float4 w4 = ws[d4];
        u64t kk[4], wa[4], wb[4];
        kk[0] = pack2(k4.x, k4.x); kk[1] = pack2(k4.y, k4.y);
        kk[2] = pack2(k4.z, k4.z); kk[3] = pack2(k4.w, k4.w);
        wa[0] = pack2(0.55f*w4.x, 0.55f*w4.x); wb[0] = pack2(0.45f*w4.x, 0.45f*w4.x);
        wa[1] = pack2(0.55f*w4.y, 0.55f*w4.y); wb[1] = pack2(0.45f*w4.y, 0.45f*w4.y);
        wa[2] = pack2(0.55f*w4.z, 0.55f*w4.z); wb[2] = pack2(0.45f*w4.z, 0.45f*w4.z);
        wa[3] = pack2(0.55f*w4.w, 0.55f*w4.w); wb[3] = pack2(0.45f*w4.w, 0.45f*w4.w);
        #pragma unroll
        for (int bp2 = 0; bp2 < 8; bp2++) {
            #pragma unroll
            for (int i = 0; i < 4; i++) {
                ulonglong2 q = *(const ulonglong2*)&spq[d4 * 4 + i][4 * bp2];
                u64t x0 = add2(q.x, kk[i]);
                acc2[2*bp2]   = fma2(x0, wa[i], acc2[2*bp2]);
                acc2[2*bp2]   = fma2(abs2(x0), wb[i], acc2[2*bp2]);
                u64t x1 = add2(q.y, kk[i]);
                acc2[2*bp2+1] = fma2(x1, wa[i], acc2[2*bp2+1]);
                acc2[2*bp2+1] = fma2(abs2(x1), wb[i], acc2[2*bp2+1]);
            }
        }
    }

    const float b2 = *b2p;
    float vals[32];
    #pragma unroll
    for (int p = 0; p < 16; p++) {
        float2 a = unpack2(acc2[p]);
        vals[2*p]   = (a.x + b2) * 2.0f;   // /TEMP, TEMP=0.5
        vals[2*p+1] = (a.y + b2) * 2.0f;
    }
    if (n < N_) {
        #pragma unroll
        for (int b = 0; b < 32; b++) g_m[(b0 + b) * N_ + n] = vals[b];
    }
    // fused per-b max (clamped-n duplicates are real row values: max unaffected)
    #pragma unroll
    for (int b = 0; b < 32; b++) {
        float m = vals[b];
        m = fmaxf(m, __shfl_xor_sync(0xffffffffu, m, 16));
        m = fmaxf(m, __shfl_xor_sync(0xffffffffu, m, 8));
        m = fmaxf(m, __shfl_xor_sync(0xffffffffu, m, 4));
        m = fmaxf(m, __shfl_xor_sync(0xffffffffu, m, 2));
        m = fmaxf(m, __shfl_xor_sync(0xffffffffu, m, 1));
        if (lane == 0) atomicMax(&g_mmax_bits[b0 + b], enc_f(m));
    }
}

// ---------------- K4: gumbel argmax (threefry2x32 partitionable) ----------------
#define TFR(r) { x0 += x1; x1 = __funnelshift_l(x1, x1, (r)); x1 ^= x0; }

__device__ __forceinline__ unsigned threefry_bits(unsigned idx) {
    const unsigned ks1 = 42u, ks2 = 0x1BD11BF0u;   // ks0 = 0
    unsigned x0 = 0u;
    unsigned x1 = idx + ks1;
    TFR(13) TFR(15) TFR(26) TFR(6);  x0 += ks1; x1 += ks2 + 1u;
    TFR(17) TFR(29) TFR(16) TFR(24); x0 += ks2; x1 += 0u  + 2u;
    TFR(13) TFR(15) TFR(26) TFR(6);  x0 += 0u;  x1 += ks1 + 3u;
    TFR(17) TFR(29) TFR(16) TFR(24); x0 += ks1; x1 += ks2 + 4u;
    TFR(13) TFR(15) TFR(26) TFR(6);  x0 += ks2; x1 += 0u  + 5u;
    return x0 ^ x1;
}

__global__ __launch_bounds__(256) void k_argmax() {
    const int row = blockIdx.x;            // b*KSEL + k
    const int b = row / KSEL_;
    const float* mrow = g_m + b * N_;
    const float mmax = dec_f(g_mmax_bits[b]);
    __shared__ unsigned s_uthb;            // bits of positive-float u-threshold
    __shared__ float szred[256];
    __shared__ int   sired[256];
    const int tid = threadIdx.x;
    if (tid == 0) s_uthb = 0u;             // uth=0 -> no prune initially
    __syncthreads();

    const unsigned base = (unsigned)row * (unsigned)N_;
    float lbest = -1e30f;
    int   libest = 0x7fffffff;

    for (int j = 0; j < 79; j++) {
        const float uth = __uint_as_float(*(volatile unsigned*)&s_uthb);
        const int n = j * 256 + tid;
        if (n < N_) {
            unsigned bits = threefry_bits(base + (unsigned)n);
            float f = __uint_as_float((bits >> 9) | 0x3f800000u) - 1.0f;
            float u = fmaxf(f, 1.17549435e-38f);
            if (u > uth) {
                float g = -logf(-logf(u));          // bit-matches XLA path
                float z = mrow[n] + g;
                if (z > lbest || (z == lbest && n < libest)) {
                    lbest = z; libest = n;
                    // conservative threshold from local best (monotone, margined)
                    float nuth = expf(-expf(-(z - mmax))) - 2e-6f;
                    if (nuth > 0.f) atomicMax(&s_uthb, __float_as_uint(nuth));
                }
            }
        }
    }
    szred[tid] = lbest; sired[tid] = libest;
    __syncthreads();
    for (int s = 128; s > 0; s >>= 1) {
        if (tid < s) {
            float oz = szred[tid + s]; int oi = sired[tid + s];
            if (oz > szred[tid] || (oz == szred[tid] && oi < sired[tid])) {
                szred[tid] = oz; sired[tid] = oi;
            }
        }
        __syncthreads();
    }
    if (tid == 0) g_sel[row] = sired[0];
}

// ---------------- K5: gather + scores + softmax + context ----------------
__global__ __launch_bounds__(128) void k_context(float* __restrict__ out) {
    const int b = blockIdx.x, d = threadIdx.x;
    const int lane = d & 31, w = d >> 5;
    __shared__ int ssel[KSEL_];
    __shared__ float part[4][KSEL_];
    __shared__ float ssc[KSEL_];
    if (d < KSEL_) ssel[d] = g_sel[b * KSEL_ + d];
    __syncthreads();
    const float q = g_Q[b * D_ + d];
    float v[KSEL_];
    #pragma unroll
    for (int k = 0; k < KSEL_; k++) v[k] = g_V[ssel[k] * D_ + d];
    #pragma unroll
    for (int k = 0; k < KSEL_; k++) {
        float p = q * v[k];
        p += __shfl_down_sync(0xffffffffu, p, 16);
        p += __shfl_down_sync(0xffffffffu, p, 8);
        p += __shfl_down_sync(0xffffffffu, p, 4);
        p += __shfl_down_sync(0xffffffffu, p, 2);
        p += __shfl_down_sync(0xffffffffu, p, 1);
        if (lane == 0) part[w][k] = p;
    }
    __syncthreads();
    if (d < KSEL_)
        ssc[d] = (part[0][d] + part[1][d] + part[2][d] + part[3][d]) / sqrtf(128.0f);
    __syncthreads();
    float mx = -1e30f;
    #pragma unroll
    for (int k = 0; k < KSEL_; k++) mx = fmaxf(mx, ssc[k]);
    float e[KSEL_], sum = 0.f;
    #pragma unroll
    for (int k = 0; k < KSEL_; k++) { e[k] = expf(ssc[k] - mx); sum += e[k]; }
    const float inv = 1.0f / sum;
    float ctx = 0.f;
    #pragma unroll
    for (int k = 0; k < KSEL_; k++) ctx = fmaf(e[k] * inv, v[k], ctx);
    out[b * D_ + d] = ctx;
}

// ---------------- launch ----------------
extern "C" void kernel_launch(void* const* d_in, const int* in_sizes, int n_in,
                              void* d_out, int out_size) {
    const float* pe = (const float*)d_in[0];
    const float* ge = (const float*)d_in[1];
    const float* Wq = (const float*)d_in[2];
    const float* bq = (const float*)d_in[3];
    const float* Wk = (const float*)d_in[4];
    const float* bk = (const float*)d_in[5];
    const float* Wv = (const float*)d_in[6];
    const float* bv = (const float*)d_in[7];
    const float* W1 = (const float*)d_in[8];
    const float* b1 = (const float*)d_in[9];
    const float* w2 = (const float*)d_in[10];
    const float* b2 = (const float*)d_in[11];

    k_qprep<<<B_, 128>>>(pe, Wq, bq, W1);
    k_gene<<<N_ / 16, 64>>>(ge, Wk, bk, Wv, bv, W1, b1);
    k_logits<<<dim3((N_ + 127) / 128, 2), 128>>>(w2, b2);
    k_argmax<<<B_ * KSEL_, 256>>>();
    k_context<<<B_, 128>>>((float*)d_out);
}

// round 7
// speedup vs baseline: 1.1077x; 1.0482x over previous
#include <cuda_runtime.h>
#include <cstdint>
#include <math.h>

#define B_    64
#define N_    20000
#define F1_   512
#define F2_   256
#define D_    128
#define KSEL_ 20

typedef unsigned long long u64t;

// ---------------- static device scratch (no allocations allowed) ----------------
__device__ float    g_kpb[N_ * D_];      // ge@Wf + bias  (== Km@W1[D:] + b1 re-associated)
__device__ float    g_Q[B_ * D_];        // Q = pe@Wq + bq
__device__ float    g_qp2f[D_ * B_];     // q_part, packed layout [d][b]
__device__ float    g_m[B_ * N_];        // logits = sim / TEMP
__device__ unsigned g_mmax_bits[B_];     // per-b max of logits, encoded
__device__ int      g_sel[B_ * KSEL_];   // argmax indices
__device__ float    g_Wf[F2_ * D_];      // fused weight Wk@W1[D:]
__device__ float    g_bias[D_];          // bk@W1[D:] + b1

// ---------------- f32x2 packed helpers (sm_103a) ----------------
__device__ __forceinline__ u64t pack2(float lo, float hi) {
    u64t r; asm("mov.b64 %0,{%1,%2};" : "=l"(r) : "f"(lo), "f"(hi)); return r;
}
__device__ __forceinline__ float2 unpack2(u64t v) {
    float2 r; asm("mov.b64 {%0,%1},%2;" : "=f"(r.x), "=f"(r.y) : "l"(v)); return r;
}
__device__ __forceinline__ u64t add2(u64t a, u64t b) {
    u64t r; asm("add.rn.f32x2 %0,%1,%2;" : "=l"(r) : "l"(a), "l"(b)); return r;
}
__device__ __forceinline__ u64t fma2(u64t a, u64t b, u64t c) {
    u64t r; asm("fma.rn.f32x2 %0,%1,%2,%3;" : "=l"(r) : "l"(a), "l"(b), "l"(c)); return r;
}
__device__ __forceinline__ u64t abs2(u64t a) { return a & 0x7FFFFFFF7FFFFFFFULL; }

__device__ __forceinline__ unsigned enc_f(float z) {
    unsigned u = __float_as_uint(z);
    return (u & 0x80000000u) ? ~u : (u | 0x80000000u);
}
__device__ __forceinline__ float dec_f(unsigned e) {
    unsigned u = (e & 0x80000000u) ? (e & 0x7fffffffu) : ~e;
    return __uint_as_float(u);
}

// ---------------- K1: Q, q_part (packed layout), mmax init ----------------
__global__ __launch_bounds__(128) void k_qprep(const float* __restrict__ pe,
                                               const float* __restrict__ Wq,
                                               const float* __restrict__ bq,
                                               const float* __restrict__ W1) {
    __shared__ float pes[F1_];
    __shared__ float Qs[D_];
    const int b = blockIdx.x, d = threadIdx.x;
    if (d == 0) g_mmax_bits[b] = 0u;           // reset per replay
    for (int i = d; i < F1_; i += 128) pes[i] = pe[b * F1_ + i];
    __syncthreads();
    float acc = bq[d];
    #pragma unroll 4
    for (int f = 0; f < F1_; f++) acc = fmaf(pes[f], Wq[f * D_ + d], acc);
    g_Q[b * D_ + d] = acc;
    Qs[d] = acc;
    __syncthreads();
    float a2 = 0.f;
    #pragma unroll 4
    for (int j = 0; j < D_; j++) a2 = fmaf(Qs[j], W1[j * D_ + d], a2);
    g_qp2f[d * B_ + b] = a2;
}

// ---------------- K1b: fused weight Wf = Wk @ W1[D:], bias = bk@W1[D:] + b1 ----------------
// blocks 0..255: one f-row of Wf each; block 256: bias.
__global__ __launch_bounds__(128) void k_wfuse(const float* __restrict__ Wk,
                                               const float* __restrict__ bk,
                                               const float* __restrict__ W1,
                                               const float* __restrict__ b1) {
    __shared__ float rowv[D_];
    const int d = threadIdx.x;
    const float* W1p = W1 + D_ * D_;
    if (blockIdx.x < 256) {
        const int f = blockIdx.x;
        rowv[d] = Wk[f * D_ + d];
        __syncthreads();
        float acc = 0.f;
        #pragma unroll 4
        for (int j = 0; j < D_; j++) acc = fmaf(rowv[j], W1p[j * D_ + d], acc);
        g_Wf[f * D_ + d] = acc;
    } else {
        rowv[d] = bk[d];
        __syncthreads();
        float acc = b1[d];
        #pragma unroll 4
        for (int j = 0; j < D_; j++) acc = fmaf(rowv[j], W1p[j * D_ + d], acc);
        g_bias[d] = acc;
    }
}

// ---------------- K2: kpb = ge @ Wf + bias ----------------
// 128 threads; thread owns output column d; 16 gene rows per block.
__global__ __launch_bounds__(128) void k_gene(const float* __restrict__ ge) {
    __shared__ __align__(16) float ges[16][256];
    const int d = threadIdx.x;
    const int n0 = blockIdx.x * 16;

    const float4* ge4 = (const float4*)(ge + n0 * F2_);
    for (int i = d; i < 16 * 64; i += 128) {
        int r = i >> 6, c = i & 63;
        *(float4*)&ges[r][c * 4] = ge4[r * 64 + c];
    }
    __syncthreads();

    float acc[16];
    const float bd = g_bias[d];
    #pragma unroll
    for (int r = 0; r < 16; r++) acc[r] = bd;

    for (int f4 = 0; f4 < 64; f4++) {
        const int f = f4 * 4;
        float w0 = g_Wf[(f+0)*D_ + d], w1 = g_Wf[(f+1)*D_ + d];
        float w2_ = g_Wf[(f+2)*D_ + d], w3 = g_Wf[(f+3)*D_ + d];
        #pragma unroll
        for (int r = 0; r < 16; r++) {
            float4 x = *(const float4*)&ges[r][f];
            acc[r] = fmaf(x.x, w0, acc[r]); acc[r] = fmaf(x.y, w1, acc[r]);
            acc[r] = fmaf(x.z, w2_, acc[r]); acc[r] = fmaf(x.w, w3, acc[r]);
        }
    }
    #pragma unroll
    for (int r = 0; r < 16; r++) g_kpb[(n0 + r) * D_ + d] = acc[r];
}

// ---------------- K3: logits m[b,n] with f32x2, fused per-b max ----------------
// lrelu(x) = 0.55x + 0.45|x| -> w*lrelu(x) = (0.55w)x + (0.45w)|x|
__global__ __launch_bounds__(128) void k_logits(const float* __restrict__ w2,
                                                const float* __restrict__ b2p) {
    __shared__ __align__(16) float spq[D_][32];
    __shared__ float4 ws[32];
    const int tid = threadIdx.x;
    const int lane = tid & 31;
    const int b0 = blockIdx.y * 32;

    for (int i = tid; i < 1024; i += 128) {
        int d = i >> 3, c = i & 7;
        *(float4*)&spq[d][4 * c] = *(const float4*)&g_qp2f[d * B_ + b0 + 4 * c];
    }
    if (tid < 32) ws[tid] = ((const float4*)w2)[tid];
    __syncthreads();

    const int n = blockIdx.x * 128 + tid;
    const int nc = n < N_ ? n : N_ - 1;
    const float4* kp4 = (const float4*)(g_kpb + nc * D_);

    u64t acc2[16];
    #pragma unroll
    for (int p = 0; p < 16; p++) acc2[p] = 0ull;

    for (int d4 = 0; d4 < 32; d4++) {
        float4 k4 = kp4[d4];
        float4 w4 = ws[d4];
        u64t kk[4], wa[4], wb[4];
        kk[0] = pack2(k4.x, k4.x); kk[1] = pack2(k4.y, k4.y);
        kk[2] = pack2(k4.z, k4.z); kk[3] = pack2(k4.w, k4.w);
        wa[0] = pack2(0.55f*w4.x, 0.55f*w4.x); wb[0] = pack2(0.45f*w4.x, 0.45f*w4.x);
        wa[1] = pack2(0.55f*w4.y, 0.55f*w4.y); wb[1] = pack2(0.45f*w4.y, 0.45f*w4.y);
        wa[2] = pack2(0.55f*w4.z, 0.55f*w4.z); wb[2] = pack2(0.45f*w4.z, 0.45f*w4.z);
        wa[3] = pack2(0.55f*w4.w, 0.55f*w4.w); wb[3] = pack2(0.45f*w4.w, 0.45f*w4.w);
        #pragma unroll
        for (int bp2 = 0; bp2 < 8; bp2++) {
            #pragma unroll
            for (int i = 0; i < 4; i++) {
                ulonglong2 q = *(const ulonglong2*)&spq[d4 * 4 + i][4 * bp2];
                u64t x0 = add2(q.x, kk[i]);
                acc2[2*bp2]   = fma2(x0, wa[i], acc2[2*bp2]);
                acc2[2*bp2]   = fma2(abs2(x0), wb[i], acc2[2*bp2]);
                u64t x1 = add2(q.y, kk[i]);
                acc2[2*bp2+1] = fma2(x1, wa[i], acc2[2*bp2+1]);
                acc2[2*bp2+1] = fma2(abs2(x1), wb[i], acc2[2*bp2+1]);
            }
        }
    }

    const float b2 = *b2p;
    float vals[32];
    #pragma unroll
    for (int p = 0; p < 16; p++) {
        float2 a = unpack2(acc2[p]);
        vals[2*p]   = (a.x + b2) * 2.0f;   // /TEMP, TEMP=0.5
        vals[2*p+1] = (a.y + b2) * 2.0f;
    }
    if (n < N_) {
        #pragma unroll
        for (int b = 0; b < 32; b++) g_m[(b0 + b) * N_ + n] = vals[b];
    }
    #pragma unroll
    for (int b = 0; b < 32; b++) {
        float m = vals[b];
        m = fmaxf(m, __shfl_xor_sync(0xffffffffu, m, 16));
        m = fmaxf(m, __shfl_xor_sync(0xffffffffu, m, 8));
        m = fmaxf(m, __shfl_xor_sync(0xffffffffu, m, 4));
        m = fmaxf(m, __shfl_xor_sync(0xffffffffu, m, 2));
        m = fmaxf(m, __shfl_xor_sync(0xffffffffu, m, 1));
        if (lane == 0) atomicMax(&g_mmax_bits[b0 + b], enc_f(m));
    }
}

// ---------------- K4: gumbel argmax (threefry2x32 partitionable) ----------------
__device__ __forceinline__ unsigned madu(unsigned a, unsigned one, unsigned c) {
    unsigned r; asm("mad.lo.s32 %0,%1,%2,%3;" : "=r"(r) : "r"(a), "r"(one), "r"(c)); return r;
}
// x0 += x1 via IMAD (fma pipe); SHF/LOP3 stay on alu pipe -> pipe balance
#define TFRM(r) { x0 = madu(x1, one, x0); x1 = __funnelshift_l(x1, x1, (r)); x1 ^= x0; }

__device__ __forceinline__ unsigned threefry_bits(unsigned idx, unsigned one) {
    const unsigned ks1 = 42u, ks2 = 0x1BD11BF0u;   // ks0 = 0
    unsigned x0 = 0u;
    unsigned x1 = idx + ks1;
    TFRM(13) TFRM(15) TFRM(26) TFRM(6);  x0 += ks1; x1 += ks2 + 1u;
    TFRM(17) TFRM(29) TFRM(16) TFRM(24); x0 += ks2; x1 += 0u  + 2u;
    TFRM(13) TFRM(15) TFRM(26) TFRM(6);  x0 += 0u;  x1 += ks1 + 3u;
    TFRM(17) TFRM(29) TFRM(16) TFRM(24); x0 += ks1; x1 += ks2 + 4u;
    TFRM(13) TFRM(15) TFRM(26) TFRM(6);  x0 += ks2; x1 += 0u  + 5u;
    return x0 ^ x1;
}

__global__ __launch_bounds__(256) void k_argmax() {
    const int row = blockIdx.x;            // b*KSEL + k
    const int b = row / KSEL_;
    const float* mrow = g_m + b * N_;
    const unsigned eb = g_mmax_bits[b];
    const float mmax = dec_f(eb);
    const unsigned one = (eb >> 31) | 1u;  // == 1 at runtime, opaque to ptxas
    __shared__ unsigned s_uthb;
    __shared__ float szred[256];
    __shared__ int   sired[256];
    const int tid = threadIdx.x;
    if (tid == 0) s_uthb = 0u;
    __syncthreads();

    const unsigned base = (unsigned)row * (unsigned)N_;
    float lbest = -1e30f;
    int   libest = 0x7fffffff;

    for (int j = 0; j < 79; j++) {
        const float uth = __uint_as_float(*(volatile unsigned*)&s_uthb);
        const int n = j * 256 + tid;
        if (n < N_) {
            unsigned bits = threefry_bits(base + (unsigned)n, one);
            float f = __uint_as_float((bits >> 9) | 0x3f800000u) - 1.0f;
            float u = fmaxf(f, 1.17549435e-38f);
            if (u > uth) {
                float g = -logf(-logf(u));
                float z = mrow[n] + g;
                if (z > lbest || (z == lbest && n < libest)) {
                    lbest = z; libest = n;
                    float nuth = expf(-expf(-(z - mmax))) - 2e-6f;
                    if (nuth > 0.f) atomicMax(&s_uthb, __float_as_uint(nuth));
                }
            }
        }
    }
    szred[tid] = lbest; sired[tid] = libest;
    __syncthreads();
    for (int s = 128; s > 0; s >>= 1) {
        if (tid < s) {
            float oz = szred[tid + s]; int oi = sired[tid + s];
            if (oz > szred[tid] || (oz == szred[tid] && oi < sired[tid])) {
                szred[tid] = oz; sired[tid] = oi;
            }
        }
        __syncthreads();
    }
    if (tid == 0) g_sel[row] = sired[0];
}

// ---------------- K5: on-demand V rows + scores + softmax + context ----------------
__global__ __launch_bounds__(128) void k_context(const float* __restrict__ ge,
                                                 const float* __restrict__ Wv,
                                                 const float* __restrict__ bv,
                                                 float* __restrict__ out) {
    const int b = blockIdx.x, d = threadIdx.x;
    const int lane = d & 31, w = d >> 5;
    __shared__ int ssel[KSEL_];
    __shared__ __align__(16) float ges[KSEL_][256];
    __shared__ float part[4][KSEL_];
    __shared__ float ssc[KSEL_];
    if (d < KSEL_) ssel[d] = g_sel[b * KSEL_ + d];
    __syncthreads();
    // stage the 20 selected gene rows
    for (int i = d; i < KSEL_ * 64; i += 128) {
        int k = i >> 6, c = i & 63;
        *(float4*)&ges[k][c * 4] = *(const float4*)(ge + ssel[k] * F2_ + c * 4);
    }
    __syncthreads();

    // V rows on demand: v[k] = ge[sel[k]] . Wv[:,d] + bv[d]
    float v[KSEL_];
    const float bvd = bv[d];
    #pragma unroll
    for (int k = 0; k < KSEL_; k++) v[k] = bvd;
    for (int f = 0; f < F2_; f++) {
        const float wv = Wv[f * D_ + d];
        #pragma unroll
        for (int k = 0; k < KSEL_; k++) v[k] = fmaf(ges[k][f], wv, v[k]);
    }

    const float q = g_Q[b * D_ + d];
    #pragma unroll
    for (int k = 0; k < KSEL_; k++) {
        float p = q * v[k];
        p += __shfl_down_sync(0xffffffffu, p, 16);
        p += __shfl_down_sync(0xffffffffu, p, 8);
        p += __shfl_down_sync(0xffffffffu, p, 4);
        p += __shfl_down_sync(0xffffffffu, p, 2);
        p += __shfl_down_sync(0xffffffffu, p, 1);
        if (lane == 0) part[w][k] = p;
    }
    __syncthreads();
    if (d < KSEL_)
        ssc[d] = (part[0][d] + part[1][d] + part[2][d] + part[3][d]) / sqrtf(128.0f);
    __syncthreads();
    float mx = -1e30f;
    #pragma unroll
    for (int k = 0; k < KSEL_; k++) mx = fmaxf(mx, ssc[k]);
    float e[KSEL_], sum = 0.f;
    #pragma unroll
    for (int k = 0; k < KSEL_; k++) { e[k] = expf(ssc[k] - mx); sum += e[k]; }
    const float inv = 1.0f / sum;
    float ctx = 0.f;
    #pragma unroll
    for (int k = 0; k < KSEL_; k++) ctx = fmaf(e[k] * inv, v[k], ctx);
    out[b * D_ + d] = ctx;
}

// ---------------- launch ----------------
extern "C" void kernel_launch(void* const* d_in, const int* in_sizes, int n_in,
                              void* d_out, int out_size) {
    const float* pe = (const float*)d_in[0];
    const float* ge = (const float*)d_in[1];
    const float* Wq = (const float*)d_in[2];
    const float* bq = (const float*)d_in[3];
    const float* Wk = (const float*)d_in[4];
    const float* bk = (const float*)d_in[5];
    const float* Wv = (const float*)d_in[6];
    const float* bv = (const float*)d_in[7];
    const float* W1 = (const float*)d_in[8];
    const float* b1 = (const float*)d_in[9];
    const float* w2 = (const float*)d_in[10];
    const float* b2 = (const float*)d_in[11];

    k_qprep<<<B_, 128>>>(pe, Wq, bq, W1);
    k_wfuse<<<257, 128>>>(Wk, bk, W1, b1);
    k_gene<<<N_ / 16, 128>>>(ge);
    k_logits<<<dim3((N_ + 127) / 128, 2), 128>>>(w2, b2);
    k_argmax<<<B_ * KSEL_, 256>>>();
    k_context<<<B_, 128>>>(ge, Wv, bv, (float*)d_out);
}

// round 8
// speedup vs baseline: 1.1217x; 1.0126x over previous
#include <cuda_runtime.h>
#include <cstdint>
#include <math.h>

#define B_    64
#define N_    20000
#define F1_   512
#define F2_   256
#define D_    128
#define KSEL_ 20

typedef unsigned long long u64t;

// ---------------- static device scratch (no allocations allowed) ----------------
__device__ float    g_kpb[N_ * D_];      // ge@Wf + bias  (== Km@W1[D:] + b1 re-associated)
__device__ float    g_Q[B_ * D_];        // Q = pe@Wq + bq
__device__ float    g_qp2f[D_ * B_];     // q_part, packed layout [d][b]
__device__ float    g_m[B_ * N_];        // logits = sim / TEMP
__device__ unsigned g_mmax_bits[B_];     // per-b max of logits, encoded
__device__ int      g_sel[B_ * KSEL_];   // argmax indices
__device__ __align__(16) float g_Wf4[64 * D_ * 4];  // fused weight, packed [f4][d][4]
__device__ float    g_bias[D_];          // bk@W1[D:] + b1

// ---------------- f32x2 packed helpers (sm_103a) ----------------
__device__ __forceinline__ u64t pack2(float lo, float hi) {
    u64t r; asm("mov.b64 %0,{%1,%2};" : "=l"(r) : "f"(lo), "f"(hi)); return r;
}
__device__ __forceinline__ float2 unpack2(u64t v) {
    float2 r; asm("mov.b64 {%0,%1},%2;" : "=f"(r.x), "=f"(r.y) : "l"(v)); return r;
}
__device__ __forceinline__ u64t add2(u64t a, u64t b) {
    u64t r; asm("add.rn.f32x2 %0,%1,%2;" : "=l"(r) : "l"(a), "l"(b)); return r;
}
__device__ __forceinline__ u64t fma2(u64t a, u64t b, u64t c) {
    u64t r; asm("fma.rn.f32x2 %0,%1,%2,%3;" : "=l"(r) : "l"(a), "l"(b), "l"(c)); return r;
}
__device__ __forceinline__ u64t abs2(u64t a) { return a & 0x7FFFFFFF7FFFFFFFULL; }

__device__ __forceinline__ unsigned enc_f(float z) {
    unsigned u = __float_as_uint(z);
    return (u & 0x80000000u) ? ~u : (u | 0x80000000u);
}
__device__ __forceinline__ float dec_f(unsigned e) {
    unsigned u = (e & 0x80000000u) ? (e & 0x7fffffffu) : ~e;
    return __uint_as_float(u);
}

// ---------------- K1: Q, q_part (packed layout), mmax init ----------------
__global__ __launch_bounds__(128) void k_qprep(const float* __restrict__ pe,
                                               const float* __restrict__ Wq,
                                               const float* __restrict__ bq,
                                               const float* __restrict__ W1) {
    __shared__ float pes[F1_];
    __shared__ float Qs[D_];
    const int b = blockIdx.x, d = threadIdx.x;
    if (d == 0) g_mmax_bits[b] = 0u;           // reset per replay
    for (int i = d; i < F1_; i += 128) pes[i] = pe[b * F1_ + i];
    __syncthreads();
    float acc = bq[d];
    #pragma unroll 4
    for (int f = 0; f < F1_; f++) acc = fmaf(pes[f], Wq[f * D_ + d], acc);
    g_Q[b * D_ + d] = acc;
    Qs[d] = acc;
    __syncthreads();
    float a2 = 0.f;
    #pragma unroll 4
    for (int j = 0; j < D_; j++) a2 = fmaf(Qs[j], W1[j * D_ + d], a2);
    g_qp2f[d * B_ + b] = a2;
}

// ---------------- K1b: fused weight Wf = Wk @ W1[D:] (packed f4 layout), bias ----------------
__global__ __launch_bounds__(128) void k_wfuse(const float* __restrict__ Wk,
                                               const float* __restrict__ bk,
                                               const float* __restrict__ W1,
                                               const float* __restrict__ b1) {
    __shared__ float rowv[D_];
    const int d = threadIdx.x;
    const float* W1p = W1 + D_ * D_;
    if (blockIdx.x < 256) {
        const int f = blockIdx.x;
        rowv[d] = Wk[f * D_ + d];
        __syncthreads();
        float acc = 0.f;
        #pragma unroll 4
        for (int j = 0; j < D_; j++) acc = fmaf(rowv[j], W1p[j * D_ + d], acc);
        g_Wf4[(((f >> 2) * D_) + d) * 4 + (f & 3)] = acc;   // packed [f4][d][4]
    } else {
        rowv[d] = bk[d];
        __syncthreads();
        float acc = b1[d];
        #pragma unroll 4
        for (int j = 0; j < D_; j++) acc = fmaf(rowv[j], W1p[j * D_ + d], acc);
        g_bias[d] = acc;
    }
}

// ---------------- K2: kpb = ge @ Wf + bias ----------------
// 128 threads; thread owns output column d; 16 gene rows per block.
// Weight loads: 1 LDG.128 per f4 from the packed layout.
__global__ __launch_bounds__(128) void k_gene(const float* __restrict__ ge) {
    __shared__ __align__(16) float ges[16][256];
    const int d = threadIdx.x;
    const int n0 = blockIdx.x * 16;

    const float4* ge4 = (const float4*)(ge + n0 * F2_);
    for (int i = d; i < 16 * 64; i += 128) {
        int r = i >> 6, c = i & 63;
        *(float4*)&ges[r][c * 4] = ge4[r * 64 + c];
    }
    __syncthreads();

    float acc[16];
    const float bd = g_bias[d];
    #pragma unroll
    for (int r = 0; r < 16; r++) acc[r] = bd;

    const float4* Wf4 = (const float4*)g_Wf4;
    for (int f4 = 0; f4 < 64; f4++) {
        const float4 w = Wf4[f4 * D_ + d];
        const int f = f4 * 4;
        #pragma unroll
        for (int r = 0; r < 16; r++) {
            float4 x = *(const float4*)&ges[r][f];
            acc[r] = fmaf(x.x, w.x, acc[r]); acc[r] = fmaf(x.y, w.y, acc[r]);
            acc[r] = fmaf(x.z, w.z, acc[r]); acc[r] = fmaf(x.w, w.w, acc[r]);
        }
    }
    #pragma unroll
    for (int r = 0; r < 16; r++) g_kpb[(n0 + r) * D_ + d] = acc[r];
}

// ---------------- K3: logits m[b,n] -- 16 b per block, split accumulators ----------------
// lrelu(x) = 0.55x + 0.45|x| -> w*lrelu(x) = (0.55w)x + (0.45w)|x|
__global__ __launch_bounds__(128) void k_logits(const float* __restrict__ w2,
                                                const float* __restrict__ b2p) {
    __shared__ __align__(16) float spq[D_][16];   // [d][b_local], 16 b this block
    __shared__ float4 ws[32];
    const int tid = threadIdx.x;
    const int lane = tid & 31;
    const int b0 = blockIdx.y * 16;

    for (int i = tid; i < 512; i += 128) {        // 128 d x 4 float4
        int d = i >> 2, j = i & 3;
        *(float4*)&spq[d][4 * j] = *(const float4*)&g_qp2f[d * B_ + b0 + 4 * j];
    }
    if (tid < 32) ws[tid] = ((const float4*)w2)[tid];
    __syncthreads();

    const int n = blockIdx.x * 128 + tid;
    const int nc = n < N_ ? n : N_ - 1;
    const float4* kp4 = (const float4*)(g_kpb + nc * D_);

    u64t accA[8], accB[8];                        // 8 b-pairs; A: x-part, B: |x|-part
    #pragma unroll
    for (int p = 0; p < 8; p++) { accA[p] = 0ull; accB[p] = 0ull; }

    for (int d4 = 0; d4 < 32; d4++) {
        float4 k4 = kp4[d4];
        float4 w4 = ws[d4];
        const float kv[4] = {k4.x, k4.y, k4.z, k4.w};
        const float wv[4] = {w4.x, w4.y, w4.z, w4.w};
        #pragma unroll
        for (int i = 0; i < 4; i++) {
            const int d = d4 * 4 + i;
            u64t kk = pack2(kv[i], kv[i]);
            u64t wa = pack2(0.55f * wv[i], 0.55f * wv[i]);
            u64t wb = pack2(0.45f * wv[i], 0.45f * wv[i]);
            #pragma unroll
            for (int p = 0; p < 8; p++) {
                u64t q = *(const u64t*)&spq[d][2 * p];   // broadcast LDS.64
                u64t x = add2(q, kk);
                accA[p] = fma2(x, wa, accA[p]);
                accB[p] = fma2(abs2(x), wb, accB[p]);
            }
        }
    }

    const float b2 = *b2p;
    float vals[16];
    #pragma unroll
    for (int p = 0; p < 8; p++) {
        float2 a = unpack2(add2(accA[p], accB[p]));
        vals[2*p]   = (a.x + b2) * 2.0f;   // /TEMP, TEMP=0.5
        vals[2*p+1] = (a.y + b2) * 2.0f;
    }
    if (n < N_) {
        #pragma unroll
        for (int b = 0; b < 16; b++) g_m[(b0 + b) * N_ + n] = vals[b];
    }
    #pragma unroll
    for (int b = 0; b < 16; b++) {
        float m = vals[b];
        m = fmaxf(m, __shfl_xor_sync(0xffffffffu, m, 16));
        m = fmaxf(m, __shfl_xor_sync(0xffffffffu, m, 8));
        m = fmaxf(m, __shfl_xor_sync(0xffffffffu, m, 4));
        m = fmaxf(m, __shfl_xor_sync(0xffffffffu, m, 2));
        m = fmaxf(m, __shfl_xor_sync(0xffffffffu, m, 1));
        if (lane == 0) atomicMax(&g_mmax_bits[b0 + b], enc_f(m));
    }
}

// ---------------- K4: gumbel argmax (threefry2x32 partitionable) ----------------
__device__ __forceinline__ unsigned madu(unsigned a, unsigned one, unsigned c) {
    unsigned r; asm("mad.lo.s32 %0,%1,%2,%3;" : "=r"(r) : "r"(a), "r"(one), "r"(c)); return r;
}
// x0 += x1 via IMAD (fma pipe); SHF/LOP3 stay on alu pipe -> pipe balance
#define TFRM(r) { x0 = madu(x1, one, x0); x1 = __funnelshift_l(x1, x1, (r)); x1 ^= x0; }

__device__ __forceinline__ unsigned threefry_bits(unsigned idx, unsigned one) {
    const unsigned ks1 = 42u, ks2 = 0x1BD11BF0u;   // ks0 = 0
    unsigned x0 = 0u;
    unsigned x1 = idx + ks1;
    TFRM(13) TFRM(15) TFRM(26) TFRM(6);  x0 += ks1; x1 += ks2 + 1u;
    TFRM(17) TFRM(29) TFRM(16) TFRM(24); x0 += ks2; x1 += 0u  + 2u;
    TFRM(13) TFRM(15) TFRM(26) TFRM(6);  x0 += 0u;  x1 += ks1 + 3u;
    TFRM(17) TFRM(29) TFRM(16) TFRM(24); x0 += ks1; x1 += ks2 + 4u;
    TFRM(13) TFRM(15) TFRM(26) TFRM(6);  x0 += ks2; x1 += 0u  + 5u;
    return x0 ^ x1;
}

__global__ __launch_bounds__(256) void k_argmax() {
    const int row = blockIdx.x;            // b*KSEL + k
    const int b = row / KSEL_;
    const float* mrow = g_m + b * N_;
    const unsigned eb = g_mmax_bits[b];
    const float mmax = dec_f(eb);
    const unsigned one = (eb >> 31) | 1u;  // == 1 at runtime, opaque to ptxas
    __shared__ unsigned s_uthb;
    __shared__ float szred[256];
    __shared__ int   sired[256];
    const int tid = threadIdx.x;
    if (tid == 0) s_uthb = 0u;
    __syncthreads();

    const unsigned base = (unsigned)row * (unsigned)N_;
    float lbest = -1e30f;
    int   libest = 0x7fffffff;

    for (int j = 0; j < 79; j++) {
        const float uth = __uint_as_float(*(volatile unsigned*)&s_uthb);
        const int n = j * 256 + tid;
        if (n < N_) {
            unsigned bits = threefry_bits(base + (unsigned)n, one);
            float f = __uint_as_float((bits >> 9) | 0x3f800000u) - 1.0f;
            float u = fmaxf(f, 1.17549435e-38f);
            if (u > uth) {
                float g = -logf(-logf(u));
                float z = mrow[n] + g;
                if (z > lbest || (z == lbest && n < libest)) {
                    lbest = z; libest = n;
                    float nuth = expf(-expf(-(z - mmax))) - 2e-6f;
                    if (nuth > 0.f) atomicMax(&s_uthb, __float_as_uint(nuth));
                }
            }
        }
    }
    szred[tid] = lbest; sired[tid] = libest;
    __syncthreads();
    for (int s = 128; s > 0; s >>= 1) {
        if (tid < s) {
            float oz = szred[tid + s]; int oi = sired[tid + s];
            if (oz > szred[tid] || (oz == szred[tid] && oi < sired[tid])) {
                szred[tid] = oz; sired[tid] = oi;
            }
        }
        __syncthreads();
    }
    if (tid == 0) g_sel[row] = sired[0];
}

// ---------------- K5: on-demand V rows + scores + softmax + context ----------------
__global__ __launch_bounds__(128) void k_context(const float* __restrict__ ge,
                                                 const float* __restrict__ Wv,
                                                 const float* __restrict__ bv,
                                                 float* __restrict__ out) {
    const int b = blockIdx.x, d = threadIdx.x;
    const int lane = d & 31, w = d >> 5;
    __shared__ int ssel[KSEL_];
    __shared__ __align__(16) float ges[KSEL_][256];
    __shared__ float part[4][KSEL_];
    __shared__ float ssc[KSEL_];
    if (d < KSEL_) ssel[d] = g_sel[b * KSEL_ + d];
    __syncthreads();
    for (int i = d; i < KSEL_ * 64; i += 128) {
        int k = i >> 6, c = i & 63;
        *(float4*)&ges[k][c * 4] = *(const float4*)(ge + ssel[k] * F2_ + c * 4);
    }
    __syncthreads();

    float v[KSEL_];
    const float bvd = bv[d];
    #pragma unroll
    for (int k = 0; k < KSEL_; k++) v[k] = bvd;
    for (int f = 0; f < F2_; f++) {
        const float wv = Wv[f * D_ + d];
        #pragma unroll
        for (int k = 0; k < KSEL_; k++) v[k] = fmaf(ges[k][f], wv, v[k]);
    }

    const float q = g_Q[b * D_ + d];
    #pragma unroll
    for (int k = 0; k < KSEL_; k++) {
        float p = q * v[k];
        p += __shfl_down_sync(0xffffffffu, p, 16);
        p += __shfl_down_sync(0xffffffffu, p, 8);
        p += __shfl_down_sync(0xffffffffu, p, 4);
        p += __shfl_down_sync(0xffffffffu, p, 2);
        p += __shfl_down_sync(0xffffffffu, p, 1);
        if (lane == 0) part[w][k] = p;
    }
    __syncthreads();
    if (d < KSEL_)
        ssc[d] = (part[0][d] + part[1][d] + part[2][d] + part[3][d]) / sqrtf(128.0f);
    __syncthreads();
    float mx = -1e30f;
    #pragma unroll
    for (int k = 0; k < KSEL_; k++) mx = fmaxf(mx, ssc[k]);
    float e[KSEL_], sum = 0.f;
    #pragma unroll
    for (int k = 0; k < KSEL_; k++) { e[k] = expf(ssc[k] - mx); sum += e[k]; }
    const float inv = 1.0f / sum;
    float ctx = 0.f;
    #pragma unroll
    for (int k = 0; k < KSEL_; k++) ctx = fmaf(e[k] * inv, v[k], ctx);
    out[b * D_ + d] = ctx;
}

// ---------------- launch ----------------
extern "C" void kernel_launch(void* const* d_in, const int* in_sizes, int n_in,
                              void* d_out, int out_size) {
    const float* pe = (const float*)d_in[0];
    const float* ge = (const float*)d_in[1];
    const float* Wq = (const float*)d_in[2];
    const float* bq = (const float*)d_in[3];
    const float* Wk = (const float*)d_in[4];
    const float* bk = (const float*)d_in[5];
    const float* Wv = (const float*)d_in[6];
    const float* bv = (const float*)d_in[7];
    const float* W1 = (const float*)d_in[8];
    const float* b1 = (const float*)d_in[9];
    const float* w2 = (const float*)d_in[10];
    const float* b2 = (const float*)d_in[11];

    k_qprep<<<B_, 128>>>(pe, Wq, bq, W1);
    k_wfuse<<<257, 128>>>(Wk, bk, W1, b1);
    k_gene<<<N_ / 16, 128>>>(ge);
    k_logits<<<dim3((N_ + 127) / 128, 4), 128>>>(w2, b2);
    k_argmax<<<B_ * KSEL_, 256>>>();
    k_context<<<B_, 128>>>(ge, Wv, bv, (float*)d_out);
}

// round 9
// speedup vs baseline: 1.1499x; 1.0251x over previous
#include <cuda_runtime.h>
#include <cstdint>
#include <math.h>

#define B_    64
#define N_    20000
#define F1_   512
#define F2_   256
#define D_    128
#define KSEL_ 20

typedef unsigned long long u64t;

// ---------------- static device scratch (no allocations allowed) ----------------
__device__ float    g_kpbT[D_ * N_];     // TRANSPOSED: [d][n]  (== (Km@W1[D:]+b1)^T)
__device__ float    g_Q[B_ * D_];        // Q = pe@Wq + bq
__device__ float    g_qp2f[D_ * B_];     // q_part, packed layout [d][b]
__device__ float    g_m[B_ * N_];        // logits = sim / TEMP
__device__ unsigned g_mmax_bits[B_];     // per-b max of logits, encoded
__device__ int      g_sel[B_ * KSEL_];   // argmax indices
__device__ __align__(16) float g_Wf4[64 * D_ * 4];  // fused weight, packed [f4][d][4]
__device__ float    g_bias[D_];          // bk@W1[D:] + b1

// ---------------- f32x2 packed helpers (sm_103a) ----------------
__device__ __forceinline__ u64t pack2(float lo, float hi) {
    u64t r; asm("mov.b64 %0,{%1,%2};" : "=l"(r) : "f"(lo), "f"(hi)); return r;
}
__device__ __forceinline__ float2 unpack2(u64t v) {
    float2 r; asm("mov.b64 {%0,%1},%2;" : "=f"(r.x), "=f"(r.y) : "l"(v)); return r;
}
__device__ __forceinline__ u64t add2(u64t a, u64t b) {
    u64t r; asm("add.rn.f32x2 %0,%1,%2;" : "=l"(r) : "l"(a), "l"(b)); return r;
}
__device__ __forceinline__ u64t fma2(u64t a, u64t b, u64t c) {
    u64t r; asm("fma.rn.f32x2 %0,%1,%2,%3;" : "=l"(r) : "l"(a), "l"(b), "l"(c)); return r;
}
__device__ __forceinline__ u64t abs2(u64t a) { return a & 0x7FFFFFFF7FFFFFFFULL; }

__device__ __forceinline__ unsigned enc_f(float z) {
    unsigned u = __float_as_uint(z);
    return (u & 0x80000000u) ? ~u : (u | 0x80000000u);
}
__device__ __forceinline__ float dec_f(unsigned e) {
    unsigned u = (e & 0x80000000u) ? (e & 0x7fffffffu) : ~e;
    return __uint_as_float(u);
}

// ---------------- K1: Q, q_part (packed layout), mmax init ----------------
__global__ __launch_bounds__(128) void k_qprep(const float* __restrict__ pe,
                                               const float* __restrict__ Wq,
                                               const float* __restrict__ bq,
                                               const float* __restrict__ W1) {
    __shared__ float pes[F1_];
    __shared__ float Qs[D_];
    const int b = blockIdx.x, d = threadIdx.x;
    if (d == 0) g_mmax_bits[b] = 0u;           // reset per replay
    for (int i = d; i < F1_; i += 128) pes[i] = pe[b * F1_ + i];
    __syncthreads();
    float acc = bq[d];
    #pragma unroll 4
    for (int f = 0; f < F1_; f++) acc = fmaf(pes[f], Wq[f * D_ + d], acc);
    g_Q[b * D_ + d] = acc;
    Qs[d] = acc;
    __syncthreads();
    float a2 = 0.f;
    #pragma unroll 4
    for (int j = 0; j < D_; j++) a2 = fmaf(Qs[j], W1[j * D_ + d], a2);
    g_qp2f[d * B_ + b] = a2;
}

// ---------------- K1b: fused weight Wf = Wk @ W1[D:] (packed f4 layout), bias ----------------
__global__ __launch_bounds__(128) void k_wfuse(const float* __restrict__ Wk,
                                               const float* __restrict__ bk,
                                               const float* __restrict__ W1,
                                               const float* __restrict__ b1) {
    __shared__ float rowv[D_];
    const int d = threadIdx.x;
    const float* W1p = W1 + D_ * D_;
    if (blockIdx.x < 256) {
        const int f = blockIdx.x;
        rowv[d] = Wk[f * D_ + d];
        __syncthreads();
        float acc = 0.f;
        #pragma unroll 4
        for (int j = 0; j < D_; j++) acc = fmaf(rowv[j], W1p[j * D_ + d], acc);
        g_Wf4[(((f >> 2) * D_) + d) * 4 + (f & 3)] = acc;   // packed [f4][d][4]
    } else {
        rowv[d] = bk[d];
        __syncthreads();
        float acc = b1[d];
        #pragma unroll 4
        for (int j = 0; j < D_; j++) acc = fmaf(rowv[j], W1p[j * D_ + d], acc);
        g_bias[d] = acc;
    }
}

// ---------------- K2: kpbT = (ge @ Wf + bias)^T ----------------
// 128 threads; thread owns output column d; 32 gene rows per block.
// Output written TRANSPOSED [d][n] via smem shuffle for coalesced k_logits reads.
__global__ __launch_bounds__(128) void k_gene(const float* __restrict__ ge) {
    __shared__ __align__(16) float ges[32][256];    // 32 KB, reused as transpose buffer
    const int d = threadIdx.x;
    const int n0 = blockIdx.x * 32;

    const float4* ge4 = (const float4*)(ge + n0 * F2_);
    for (int i = d; i < 32 * 64; i += 128) {
        int r = i >> 6, c = i & 63;
        *(float4*)&ges[r][c * 4] = ge4[r * 64 + c];
    }
    __syncthreads();

    float acc[32];
    const float bd = g_bias[d];
    #pragma unroll
    for (int r = 0; r < 32; r++) acc[r] = bd;

    const float4* Wf4 = (const float4*)g_Wf4;
    for (int f4 = 0; f4 < 64; f4++) {
        const float4 w = Wf4[f4 * D_ + d];     // 1 LDG.128, coalesced
        const int f = f4 * 4;
        #pragma unroll
        for (int r = 0; r < 32; r++) {
            float4 x = *(const float4*)&ges[r][f];
            acc[r] = fmaf(x.x, w.x, acc[r]); acc[r] = fmaf(x.y, w.y, acc[r]);
            acc[r] = fmaf(x.z, w.z, acc[r]); acc[r] = fmaf(x.w, w.w, acc[r]);
        }
    }

    // transpose through smem (reuse ges): st[d][r], row pitch 33 (conflict-free)
    __syncthreads();                    // all reads of ges done
    float* st = (float*)ges;
    #pragma unroll
    for (int r = 0; r < 32; r++) st[d * 33 + r] = acc[r];
    __syncthreads();
    // thread d writes kpbT row d, 32 consecutive n -> 8 STG.128
    float* dst = g_kpbT + d * N_ + n0;
    #pragma unroll
    for (int j = 0; j < 8; j++) {
        float4 v;
        v.x = st[d * 33 + 4*j + 0]; v.y = st[d * 33 + 4*j + 1];
        v.z = st[d * 33 + 4*j + 2]; v.w = st[d * 33 + 4*j + 3];
        *(float4*)(dst + 4*j) = v;
    }
}

// ---------------- K3: logits m[b,n] -- 4 b x 4 n per thread, n-pair packing ----------------
// lrelu(x) = 0.55x + 0.45|x| -> w*lrelu(x) = (0.55w)x + (0.45w)|x|
__global__ __launch_bounds__(128) void k_logits(const float* __restrict__ w2,
                                                const float* __restrict__ b2p) {
    __shared__ u64t s_q2[D_][4];       // (q,q) duplicated pairs, [d][b_local]
    __shared__ u64t s_wa[D_], s_wb[D_];
    const int tid = threadIdx.x;
    const int lane = tid & 31;
    const int b0 = blockIdx.y * 4;

    for (int i = tid; i < 512; i += 128) {
        int d = i >> 2, j = i & 3;
        float q = g_qp2f[d * B_ + b0 + j];
        s_q2[d][j] = pack2(q, q);
    }
    if (tid < 128) {
        float w = w2[tid];
        s_wa[tid] = pack2(0.55f * w, 0.55f * w);
        s_wb[tid] = pack2(0.45f * w, 0.45f * w);
    }
    __syncthreads();

    const int n = (blockIdx.x * 128 + tid) * 4;
    const int nc = n <= N_ - 4 ? n : N_ - 4;
    const float* kT = g_kpbT + nc;

    u64t accA[4][2], accB[4][2];       // [b][n-pair]
    #pragma unroll
    for (int b = 0; b < 4; b++) { accA[b][0]=accA[b][1]=0ull; accB[b][0]=accB[b][1]=0ull; }

    for (int d = 0; d < D_; d++) {
        float4 k4 = *(const float4*)(kT + d * N_);   // coalesced LDG.128
        u64t kn01 = pack2(k4.x, k4.y);
        u64t kn23 = pack2(k4.z, k4.w);
        u64t wa = s_wa[d], wb = s_wb[d];
        #pragma unroll
        for (int b = 0; b < 4; b++) {
            u64t q = s_q2[d][b];                     // broadcast LDS.64
            u64t x0 = add2(q, kn01);
            u64t x1 = add2(q, kn23);
            accA[b][0] = fma2(x0, wa, accA[b][0]);
            accB[b][0] = fma2(abs2(x0), wb, accB[b][0]);
            accA[b][1] = fma2(x1, wa, accA[b][1]);
            accB[b][1] = fma2(abs2(x1), wb, accB[b][1]);
        }
    }

    const float b2 = *b2p;
    float vals[4][4];                  // [b][n_local]
    #pragma unroll
    for (int b = 0; b < 4; b++) {
        float2 a01 = unpack2(add2(accA[b][0], accB[b][0]));
        float2 a23 = unpack2(add2(accA[b][1], accB[b][1]));
        vals[b][0] = (a01.x + b2) * 2.0f;   // /TEMP, TEMP=0.5
        vals[b][1] = (a01.y + b2) * 2.0f;
        vals[b][2] = (a23.x + b2) * 2.0f;
        vals[b][3] = (a23.y + b2) * 2.0f;
    }
    if (n <= N_ - 4) {
        #pragma unroll
        for (int b = 0; b < 4; b++) {
            float4 v; v.x = vals[b][0]; v.y = vals[b][1]; v.z = vals[b][2]; v.w = vals[b][3];
            *(float4*)(g_m + (b0 + b) * N_ + n) = v;
        }
    }
    #pragma unroll
    for (int b = 0; b < 4; b++) {
        float m = fmaxf(fmaxf(vals[b][0], vals[b][1]), fmaxf(vals[b][2], vals[b][3]));
        m = fmaxf(m, __shfl_xor_sync(0xffffffffu, m, 16));
        m = fmaxf(m, __shfl_xor_sync(0xffffffffu, m, 8));
        m = fmaxf(m, __shfl_xor_sync(0xffffffffu, m, 4));
        m = fmaxf(m, __shfl_xor_sync(0xffffffffu, m, 2));
        m = fmaxf(m, __shfl_xor_sync(0xffffffffu, m, 1));
        if (lane == 0) atomicMax(&g_mmax_bits[b0 + b], enc_f(m));
    }
}

// ---------------- K4: gumbel argmax (threefry2x32 partitionable) ----------------
__device__ __forceinline__ unsigned madu(unsigned a, unsigned one, unsigned c) {
    unsigned r; asm("mad.lo.s32 %0,%1,%2,%3;" : "=r"(r) : "r"(a), "r"(one), "r"(c)); return r;
}
// x0 += x1 via IMAD (fma pipe); SHF/LOP3 stay on alu pipe -> pipe balance
#define TFRM(r) { x0 = madu(x1, one, x0); x1 = __funnelshift_l(x1, x1, (r)); x1 ^= x0; }

__device__ __forceinline__ unsigned threefry_bits(unsigned idx, unsigned one) {
    const unsigned ks1 = 42u, ks2 = 0x1BD11BF0u;   // ks0 = 0
    unsigned x0 = 0u;
    unsigned x1 = idx + ks1;
    TFRM(13) TFRM(15) TFRM(26) TFRM(6);  x0 += ks1; x1 += ks2 + 1u;
    TFRM(17) TFRM(29) TFRM(16) TFRM(24); x0 += ks2; x1 += 0u  + 2u;
    TFRM(13) TFRM(15) TFRM(26) TFRM(6);  x0 += 0u;  x1 += ks1 + 3u;
    TFRM(17) TFRM(29) TFRM(16) TFRM(24); x0 += ks1; x1 += ks2 + 4u;
    TFRM(13) TFRM(15) TFRM(26) TFRM(6);  x0 += ks2; x1 += 0u  + 5u;
    return x0 ^ x1;
}

__global__ __launch_bounds__(256) void k_argmax() {
    const int row = blockIdx.x;            // b*KSEL + k
    const int b = row / KSEL_;
    const float* mrow = g_m + b * N_;
    const unsigned eb = g_mmax_bits[b];
    const float mmax = dec_f(eb);
    const unsigned one = (eb >> 31) | 1u;  // == 1 at runtime, opaque to ptxas
    __shared__ unsigned s_uthb;
    __shared__ float szred[256];
    __shared__ int   sired[256];
    const int tid = threadIdx.x;
    if (tid == 0) s_uthb = 0u;
    __syncthreads();

    const unsigned base = (unsigned)row * (unsigned)N_;
    float lbest = -1e30f;
    int   libest = 0x7fffffff;

    for (int j = 0; j < 79; j++) {
        const float uth = __uint_as_float(*(volatile unsigned*)&s_uthb);
        const int n = j * 256 + tid;
        if (n < N_) {
            unsigned bits = threefry_bits(base + (unsigned)n, one);
            float f = __uint_as_float((bits >> 9) | 0x3f800000u) - 1.0f;
            float u = fmaxf(f, 1.17549435e-38f);
            if (u > uth) {
                float g = -logf(-logf(u));
                float z = mrow[n] + g;
                if (z > lbest || (z == lbest && n < libest)) {
                    lbest = z; libest = n;
                    float nuth = expf(-expf(-(z - mmax))) - 2e-6f;
                    if (nuth > 0.f) atomicMax(&s_uthb, __float_as_uint(nuth));
                }
            }
        }
    }
    szred[tid] = lbest; sired[tid] = libest;
    __syncthreads();
    for (int s = 128; s > 0; s >>= 1) {
        if (tid < s) {
            float oz = szred[tid + s]; int oi = sired[tid + s];
            if (oz > szred[tid] || (oz == szred[tid] && oi < sired[tid])) {
                szred[tid] = oz; sired[tid] = oi;
            }
        }
        __syncthreads();
    }
    if (tid == 0) g_sel[row] = sired[0];
}

// ---------------- K5: on-demand V rows + scores + softmax + context ----------------
__global__ __launch_bounds__(128) void k_context(const float* __restrict__ ge,
                                                 const float* __restrict__ Wv,
                                                 const float* __restrict__ bv,
                                                 float* __restrict__ out) {
    const int b = blockIdx.x, d = threadIdx.x;
    const int lane = d & 31, w = d >> 5;
    __shared__ int ssel[KSEL_];
    __shared__ __align__(16) float ges[KSEL_][256];
    __shared__ float part[4][KSEL_];
    __shared__ float ssc[KSEL_];
    if (d < KSEL_) ssel[d] = g_sel[b * KSEL_ + d];
    __syncthreads();
    for (int i = d; i < KSEL_ * 64; i += 128) {
        int k = i >> 6, c = i & 63;
        *(float4*)&ges[k][c * 4] = *(const float4*)(ge + ssel[k] * F2_ + c * 4);
    }
    __syncthreads();

    float v[KSEL_];
    const float bvd = bv[d];
    #pragma unroll
    for (int k = 0; k < KSEL_; k++) v[k] = bvd;
    for (int f = 0; f < F2_; f++) {
        const float wv = Wv[f * D_ + d];
        #pragma unroll
        for (int k = 0; k < KSEL_; k++) v[k] = fmaf(ges[k][f], wv, v[k]);
    }

    const float q = g_Q[b * D_ + d];
    #pragma unroll
    for (int k = 0; k < KSEL_; k++) {
        float p = q * v[k];
        p += __shfl_down_sync(0xffffffffu, p, 16);
        p += __shfl_down_sync(0xffffffffu, p, 8);
        p += __shfl_down_sync(0xffffffffu, p, 4);
        p += __shfl_down_sync(0xffffffffu, p, 2);
        p += __shfl_down_sync(0xffffffffu, p, 1);
        if (lane == 0) part[w][k] = p;
    }
    __syncthreads();
    if (d < KSEL_)
        ssc[d] = (part[0][d] + part[1][d] + part[2][d] + part[3][d]) / sqrtf(128.0f);
    __syncthreads();
    float mx = -1e30f;
    #pragma unroll
    for (int k = 0; k < KSEL_; k++) mx = fmaxf(mx, ssc[k]);
    float e[KSEL_], sum = 0.f;
    #pragma unroll
    for (int k = 0; k < KSEL_; k++) { e[k] = expf(ssc[k] - mx); sum += e[k]; }
    const float inv = 1.0f / sum;
    float ctx = 0.f;
    #pragma unroll
    for (int k = 0; k < KSEL_; k++) ctx = fmaf(e[k] * inv, v[k], ctx);
    out[b * D_ + d] = ctx;
}

// ---------------- launch ----------------
extern "C" void kernel_launch(void* const* d_in, const int* in_sizes, int n_in,
                              void* d_out, int out_size) {
    const float* pe = (const float*)d_in[0];
    const float* ge = (const float*)d_in[1];
    const float* Wq = (const float*)d_in[2];
    const float* bq = (const float*)d_in[3];
    const float* Wk = (const float*)d_in[4];
    const float* bk = (const float*)d_in[5];
    const float* Wv = (const float*)d_in[6];
    const float* bv = (const float*)d_in[7];
    const float* W1 = (const float*)d_in[8];
    const float* b1 = (const float*)d_in[9];
    const float* w2 = (const float*)d_in[10];
    const float* b2 = (const float*)d_in[11];

    k_qprep<<<B_, 128>>>(pe, Wq, bq, W1);
    k_wfuse<<<257, 128>>>(Wk, bk, W1, b1);
    k_gene<<<N_ / 32, 128>>>(ge);
    k_logits<<<dim3(40, 16), 128>>>(w2, b2);
    k_argmax<<<B_ * KSEL_, 256>>>();
    k_context<<<B_, 128>>>(ge, Wv, bv, (float*)d_out);
}

// round 10
// speedup vs baseline: 1.1706x; 1.0180x over previous
#include <cuda_runtime.h>
#include <cstdint>
#include <math.h>

#define B_    64
#define N_    20000
#define F1_   512
#define F2_   256
#define D_    128
#define KSEL_ 20

typedef unsigned long long u64t;

// ---------------- static device scratch (no allocations allowed) ----------------
__device__ float    g_kpbT[D_ * N_];     // TRANSPOSED: [d][n]  (== (Km@W1[D:]+b1)^T)
__device__ float    g_Q[B_ * D_];        // Q = pe@Wq + bq
__device__ float    g_qp2f[D_ * B_];     // q_part, packed layout [d][b]
__device__ float    g_m[B_ * N_];        // logits = sim / TEMP
__device__ unsigned g_mmax_bits[B_];     // per-b max of logits, encoded
__device__ int      g_sel[B_ * KSEL_];   // argmax indices
__device__ __align__(16) float g_Wf4[64 * D_ * 4];  // fused weight, packed [f4][d][4]
__device__ float    g_bias[D_];          // bk@W1[D:] + b1

// ---------------- f32x2 packed helpers (sm_103a) ----------------
__device__ __forceinline__ u64t pack2(float lo, float hi) {
    u64t r; asm("mov.b64 %0,{%1,%2};" : "=l"(r) : "f"(lo), "f"(hi)); return r;
}
__device__ __forceinline__ float2 unpack2(u64t v) {
    float2 r; asm("mov.b64 {%0,%1},%2;" : "=f"(r.x), "=f"(r.y) : "l"(v)); return r;
}
__device__ __forceinline__ u64t add2(u64t a, u64t b) {
    u64t r; asm("add.rn.f32x2 %0,%1,%2;" : "=l"(r) : "l"(a), "l"(b)); return r;
}
__device__ __forceinline__ u64t fma2(u64t a, u64t b, u64t c) {
    u64t r; asm("fma.rn.f32x2 %0,%1,%2,%3;" : "=l"(r) : "l"(a), "l"(b), "l"(c)); return r;
}
__device__ __forceinline__ u64t abs2(u64t a) { return a & 0x7FFFFFFF7FFFFFFFULL; }

__device__ __forceinline__ unsigned enc_f(float z) {
    unsigned u = __float_as_uint(z);
    return (u & 0x80000000u) ? ~u : (u | 0x80000000u);
}
__device__ __forceinline__ float dec_f(unsigned e) {
    unsigned u = (e & 0x80000000u) ? (e & 0x7fffffffu) : ~e;
    return __uint_as_float(u);
}

// ---------------- K1: Q, q_part (packed layout), mmax init ----------------
__global__ __launch_bounds__(128) void k_qprep(const float* __restrict__ pe,
                                               const float* __restrict__ Wq,
                                               const float* __restrict__ bq,
                                               const float* __restrict__ W1) {
    __shared__ float pes[F1_];
    __shared__ float Qs[D_];
    const int b = blockIdx.x, d = threadIdx.x;
    if (d == 0) g_mmax_bits[b] = 0u;           // reset per replay
    for (int i = d; i < F1_; i += 128) pes[i] = pe[b * F1_ + i];
    __syncthreads();
    float acc = bq[d];
    #pragma unroll 4
    for (int f = 0; f < F1_; f++) acc = fmaf(pes[f], Wq[f * D_ + d], acc);
    g_Q[b * D_ + d] = acc;
    Qs[d] = acc;
    __syncthreads();
    float a2 = 0.f;
    #pragma unroll 4
    for (int j = 0; j < D_; j++) a2 = fmaf(Qs[j], W1[j * D_ + d], a2);
    g_qp2f[d * B_ + b] = a2;
}

// ---------------- K1b: fused weight Wf = Wk @ W1[D:] (packed f4 layout), bias ----------------
__global__ __launch_bounds__(128) void k_wfuse(const float* __restrict__ Wk,
                                               const float* __restrict__ bk,
                                               const float* __restrict__ W1,
                                               const float* __restrict__ b1) {
    __shared__ float rowv[D_];
    const int d = threadIdx.x;
    const float* W1p = W1 + D_ * D_;
    if (blockIdx.x < 256) {
        const int f = blockIdx.x;
        rowv[d] = Wk[f * D_ + d];
        __syncthreads();
        float acc = 0.f;
        #pragma unroll 4
        for (int j = 0; j < D_; j++) acc = fmaf(rowv[j], W1p[j * D_ + d], acc);
        g_Wf4[(((f >> 2) * D_) + d) * 4 + (f & 3)] = acc;   // packed [f4][d][4]
    } else {
        rowv[d] = bk[d];
        __syncthreads();
        float acc = b1[d];
        #pragma unroll 4
        for (int j = 0; j < D_; j++) acc = fmaf(rowv[j], W1p[j * D_ + d], acc);
        g_bias[d] = acc;
    }
}

// ---------------- K2: kpbT = (ge @ Wf + bias)^T ----------------
__global__ __launch_bounds__(128) void k_gene(const float* __restrict__ ge) {
    __shared__ __align__(16) float ges[32][256];    // 32 KB, reused as transpose buffer
    const int d = threadIdx.x;
    const int n0 = blockIdx.x * 32;

    const float4* ge4 = (const float4*)(ge + n0 * F2_);
    for (int i = d; i < 32 * 64; i += 128) {
        int r = i >> 6, c = i & 63;
        *(float4*)&ges[r][c * 4] = ge4[r * 64 + c];
    }
    __syncthreads();

    float acc[32];
    const float bd = g_bias[d];
    #pragma unroll
    for (int r = 0; r < 32; r++) acc[r] = bd;

    const float4* Wf4 = (const float4*)g_Wf4;
    float4 wnext = Wf4[d];
    for (int f4 = 0; f4 < 64; f4++) {
        const float4 w = wnext;
        if (f4 < 63) wnext = Wf4[(f4 + 1) * D_ + d];
        const int f = f4 * 4;
        #pragma unroll
        for (int r = 0; r < 32; r++) {
            float4 x = *(const float4*)&ges[r][f];
            acc[r] = fmaf(x.x, w.x, acc[r]); acc[r] = fmaf(x.y, w.y, acc[r]);
            acc[r] = fmaf(x.z, w.z, acc[r]); acc[r] = fmaf(x.w, w.w, acc[r]);
        }
    }

    __syncthreads();                    // all reads of ges done
    float* st = (float*)ges;
    #pragma unroll
    for (int r = 0; r < 32; r++) st[d * 33 + r] = acc[r];
    __syncthreads();
    float* dst = g_kpbT + d * N_ + n0;
    #pragma unroll
    for (int j = 0; j < 8; j++) {
        float4 v;
        v.x = st[d * 33 + 4*j + 0]; v.y = st[d * 33 + 4*j + 1];
        v.z = st[d * 33 + 4*j + 2]; v.w = st[d * 33 + 4*j + 3];
        *(float4*)(dst + 4*j) = v;
    }
}

// ---------------- K3: logits m[b,n] -- 4 b x 4 n per thread, pipelined d-loop ----------------
// lrelu(x) = 0.55x + 0.45|x| -> w*lrelu(x) = (0.55w)x + (0.45w)|x|
__global__ __launch_bounds__(128) void k_logits(const float* __restrict__ w2,
                                                const float* __restrict__ b2p) {
    __shared__ u64t s_q2[D_][4];       // (q,q) duplicated pairs, [d][b_local]
    __shared__ u64t s_wa[D_], s_wb[D_];
    const int tid = threadIdx.x;
    const int lane = tid & 31;
    const int b0 = blockIdx.y * 4;

    for (int i = tid; i < 512; i += 128) {
        int d = i >> 2, j = i & 3;
        float q = g_qp2f[d * B_ + b0 + j];
        s_q2[d][j] = pack2(q, q);
    }
    {
        float w = w2[tid];
        s_wa[tid] = pack2(0.55f * w, 0.55f * w);
        s_wb[tid] = pack2(0.45f * w, 0.45f * w);
    }
    __syncthreads();

    const int n = (blockIdx.x * 128 + tid) * 4;
    const int nc = n <= N_ - 4 ? n : N_ - 4;
    const float* kT = g_kpbT + nc;

    u64t accA[4][2], accB[4][2];       // [b][n-pair]
    #pragma unroll
    for (int b = 0; b < 4; b++) { accA[b][0]=accA[b][1]=0ull; accB[b][0]=accB[b][1]=0ull; }

    // 4-deep prefetch pipeline over d
    float4 kc[4];
    #pragma unroll
    for (int i = 0; i < 4; i++) kc[i] = *(const float4*)(kT + i * N_);

    #pragma unroll 2
    for (int d0 = 0; d0 < D_ - 4; d0 += 4) {
        float4 cur[4];
        #pragma unroll
        for (int i = 0; i < 4; i++) cur[i] = kc[i];
        #pragma unroll
        for (int i = 0; i < 4; i++) kc[i] = *(const float4*)(kT + (d0 + 4 + i) * N_);
        #pragma unroll
        for (int i = 0; i < 4; i++) {
            const int d = d0 + i;
            u64t kn01 = pack2(cur[i].x, cur[i].y);
            u64t kn23 = pack2(cur[i].z, cur[i].w);
            u64t wa = s_wa[d], wb = s_wb[d];
            #pragma unroll
            for (int b = 0; b < 4; b++) {
                u64t q = s_q2[d][b];
                u64t x0 = add2(q, kn01);
                u64t x1 = add2(q, kn23);
                accA[b][0] = fma2(x0, wa, accA[b][0]);
                accB[b][0] = fma2(abs2(x0), wb, accB[b][0]);
                accA[b][1] = fma2(x1, wa, accA[b][1]);
                accB[b][1] = fma2(abs2(x1), wb, accB[b][1]);
            }
        }
    }
    // tail: d = 124..127 from kc
    #pragma unroll
    for (int i = 0; i < 4; i++) {
        const int d = D_ - 4 + i;
        u64t kn01 = pack2(kc[i].x, kc[i].y);
        u64t kn23 = pack2(kc[i].z, kc[i].w);
        u64t wa = s_wa[d], wb = s_wb[d];
        #pragma unroll
        for (int b = 0; b < 4; b++) {
            u64t q = s_q2[d][b];
            u64t x0 = add2(q, kn01);
            u64t x1 = add2(q, kn23);
            accA[b][0] = fma2(x0, wa, accA[b][0]);
            accB[b][0] = fma2(abs2(x0), wb, accB[b][0]);
            accA[b][1] = fma2(x1, wa, accA[b][1]);
            accB[b][1] = fma2(abs2(x1), wb, accB[b][1]);
        }
    }

    const float b2 = *b2p;
    float vals[4][4];                  // [b][n_local]
    #pragma unroll
    for (int b = 0; b < 4; b++) {
        float2 a01 = unpack2(add2(accA[b][0], accB[b][0]));
        float2 a23 = unpack2(add2(accA[b][1], accB[b][1]));
        vals[b][0] = (a01.x + b2) * 2.0f;   // /TEMP, TEMP=0.5
        vals[b][1] = (a01.y + b2) * 2.0f;
        vals[b][2] = (a23.x + b2) * 2.0f;
        vals[b][3] = (a23.y + b2) * 2.0f;
    }
    if (n <= N_ - 4) {
        #pragma unroll
        for (int b = 0; b < 4; b++) {
            float4 v; v.x = vals[b][0]; v.y = vals[b][1]; v.z = vals[b][2]; v.w = vals[b][3];
            *(float4*)(g_m + (b0 + b) * N_ + n) = v;
        }
    }
    #pragma unroll
    for (int b = 0; b < 4; b++) {
        float m = fmaxf(fmaxf(vals[b][0], vals[b][1]), fmaxf(vals[b][2], vals[b][3]));
        m = fmaxf(m, __shfl_xor_sync(0xffffffffu, m, 16));
        m = fmaxf(m, __shfl_xor_sync(0xffffffffu, m, 8));
        m = fmaxf(m, __shfl_xor_sync(0xffffffffu, m, 4));
        m = fmaxf(m, __shfl_xor_sync(0xffffffffu, m, 2));
        m = fmaxf(m, __shfl_xor_sync(0xffffffffu, m, 1));
        if (lane == 0) atomicMax(&g_mmax_bits[b0 + b], enc_f(m));
    }
}

// ---------------- K4: gumbel argmax (threefry2x32 partitionable) ----------------
__device__ __forceinline__ unsigned madu(unsigned a, unsigned one, unsigned c) {
    unsigned r; asm("mad.lo.s32 %0,%1,%2,%3;" : "=r"(r) : "r"(a), "r"(one), "r"(c)); return r;
}
// round-add AND key-injection adds via IMAD (fma pipe); SHF/LOP3 stay on alu pipe
#define TFRM(r) { x0 = madu(x1, one, x0); x1 = __funnelshift_l(x1, x1, (r)); x1 ^= x0; }

__device__ __forceinline__ unsigned threefry_bits(unsigned idx, unsigned one) {
    const unsigned ks1 = 42u, ks2 = 0x1BD11BF0u;   // ks0 = 0
    // round 1 with x0 == 0 simplified
    unsigned x1r = idx + ks1;
    unsigned x0 = x1r;
    unsigned x1 = __funnelshift_l(x1r, x1r, 13) ^ x0;
    TFRM(15) TFRM(26) TFRM(6);
    x0 = madu(ks1, one, x0);  x1 = madu(ks2 + 1u, one, x1);
    TFRM(17) TFRM(29) TFRM(16) TFRM(24);
    x0 = madu(ks2, one, x0);  x1 = madu(2u, one, x1);
    TFRM(13) TFRM(15) TFRM(26) TFRM(6);
    x1 = madu(ks1 + 3u, one, x1);   // x0 += 0
    TFRM(17) TFRM(29) TFRM(16) TFRM(24);
    x0 = madu(ks1, one, x0);  x1 = madu(ks2 + 4u, one, x1);
    TFRM(13) TFRM(15) TFRM(26) TFRM(6);
    x0 = madu(ks2, one, x0);  x1 = madu(5u, one, x1);
    return x0 ^ x1;
}

__global__ __launch_bounds__(256) void k_argmax() {
    const int row = blockIdx.x;            // b*KSEL + k
    const int b = row / KSEL_;
    const float* mrow = g_m + b * N_;
    const unsigned eb = g_mmax_bits[b];
    const float mmax = dec_f(eb);
    const unsigned one = (eb >> 31) | 1u;  // == 1 at runtime, opaque to ptxas
    __shared__ unsigned s_uthb;
    __shared__ float szred[256];
    __shared__ int   sired[256];
    const int tid = threadIdx.x;
    if (tid == 0) s_uthb = 0u;
    __syncthreads();

    const unsigned base = (unsigned)row * (unsigned)N_;
    float lbest = -1e30f;
    int   libest = 0x7fffffff;

    unsigned idx = base + (unsigned)tid;
    for (int j = 0; j < 79; j++, idx += 256u) {
        const float uth = __uint_as_float(*(volatile unsigned*)&s_uthb);
        const int n = j * 256 + tid;
        if (n < N_) {
            unsigned bits = threefry_bits(idx, one);
            float f = __uint_as_float((bits >> 9) | 0x3f800000u) - 1.0f;
            float u = fmaxf(f, 1.17549435e-38f);
            if (u > uth) {
                float g = -logf(-logf(u));
                float z = mrow[n] + g;
                if (z > lbest || (z == lbest && n < libest)) {
                    lbest = z; libest = n;
                    float nuth = expf(-expf(-(z - mmax))) - 2e-6f;
                    if (nuth > 0.f) atomicMax(&s_uthb, __float_as_uint(nuth));
                }
            }
        }
    }
    szred[tid] = lbest; sired[tid] = libest;
    __syncthreads();
    for (int s = 128; s > 0; s >>= 1) {
        if (tid < s) {
            float oz = szred[tid + s]; int oi = sired[tid + s];
            if (oz > szred[tid] || (oz == szred[tid] && oi < sired[tid])) {
                szred[tid] = oz; sired[tid] = oi;
            }
        }
        __syncthreads();
    }
    if (tid == 0) g_sel[row] = sired[0];
}

// ---------------- K5: on-demand V rows + scores + softmax + context ----------------
__global__ __launch_bounds__(128) void k_context(const float* __restrict__ ge,
                                                 const float* __restrict__ Wv,
                                                 const float* __restrict__ bv,
                                                 float* __restrict__ out) {
    const int b = blockIdx.x, d = threadIdx.x;
    const int lane = d & 31, w = d >> 5;
    __shared__ int ssel[KSEL_];
    __shared__ __align__(16) float ges[KSEL_][256];
    __shared__ float part[4][KSEL_];
    __shared__ float ssc[KSEL_];
    if (d < KSEL_) ssel[d] = g_sel[b * KSEL_ + d];
    __syncthreads();
    for (int i = d; i < KSEL_ * 64; i += 128) {
        int k = i >> 6, c = i & 63;
        *(float4*)&ges[k][c * 4] = *(const float4*)(ge + ssel[k] * F2_ + c * 4);
    }
    __syncthreads();

    float v[KSEL_];
    const float bvd = bv[d];
    #pragma unroll
    for (int k = 0; k < KSEL_; k++) v[k] = bvd;
    for (int f = 0; f < F2_; f++) {
        const float wv = Wv[f * D_ + d];
        #pragma unroll
        for (int k = 0; k < KSEL_; k++) v[k] = fmaf(ges[k][f], wv, v[k]);
    }

    const float q = g_Q[b * D_ + d];
    #pragma unroll
    for (int k = 0; k < KSEL_; k++) {
        float p = q * v[k];
        p += __shfl_down_sync(0xffffffffu, p, 16);
        p += __shfl_down_sync(0xffffffffu, p, 8);
        p += __shfl_down_sync(0xffffffffu, p, 4);
        p += __shfl_down_sync(0xffffffffu, p, 2);
        p += __shfl_down_sync(0xffffffffu, p, 1);
        if (lane == 0) part[w][k] = p;
    }
    __syncthreads();
    if (d < KSEL_)
        ssc[d] = (part[0][d] + part[1][d] + part[2][d] + part[3][d]) / sqrtf(128.0f);
    __syncthreads();
    float mx = -1e30f;
    #pragma unroll
    for (int k = 0; k < KSEL_; k++) mx = fmaxf(mx, ssc[k]);
    float e[KSEL_], sum = 0.f;
    #pragma unroll
    for (int k = 0; k < KSEL_; k++) { e[k] = expf(ssc[k] - mx); sum += e[k]; }
    const float inv = 1.0f / sum;
    float ctx = 0.f;
    #pragma unroll
    for (int k = 0; k < KSEL_; k++) ctx = fmaf(e[k] * inv, v[k], ctx);
    out[b * D_ + d] = ctx;
}

// ---------------- launch ----------------
extern "C" void kernel_launch(void* const* d_in, const int* in_sizes, int n_in,
                              void* d_out, int out_size) {
    const float* pe = (const float*)d_in[0];
    const float* ge = (const float*)d_in[1];
    const float* Wq = (const float*)d_in[2];
    const float* bq = (const float*)d_in[3];
    const float* Wk = (const float*)d_in[4];
    const float* bk = (const float*)d_in[5];
    const float* Wv = (const float*)d_in[6];
    const float* bv = (const float*)d_in[7];
    const float* W1 = (const float*)d_in[8];
    const float* b1 = (const float*)d_in[9];
    const float* w2 = (const float*)d_in[10];
    const float* b2 = (const float*)d_in[11];

    k_qprep<<<B_, 128>>>(pe, Wq, bq, W1);
    k_wfuse<<<257, 128>>>(Wk, bk, W1, b1);
    k_gene<<<N_ / 32, 128>>>(ge);
    k_logits<<<dim3(40, 16), 128>>>(w2, b2);
    k_argmax<<<B_ * KSEL_, 256>>>();
    k_context<<<B_, 128>>>(ge, Wv, bv, (float*)d_out);
}

// round 11
// speedup vs baseline: 1.2119x; 1.0353x over previous
#include <cuda_runtime.h>
#include <cstdint>
#include <math.h>

#define B_    64
#define N_    20000
#define F1_   512
#define F2_   256
#define D_    128
#define KSEL_ 20

typedef unsigned long long u64t;

// ---------------- static device scratch (no allocations allowed) ----------------
__device__ float    g_kpbT[D_ * N_];     // TRANSPOSED: [d][n]  (== (Km@W1[D:]+b1)^T)
__device__ float    g_Q[B_ * D_];        // Q = pe@Wq + bq
__device__ float    g_qp2f[D_ * B_];     // q_part, packed layout [d][b]
__device__ float    g_m[B_ * N_];        // logits = sim / TEMP
__device__ unsigned g_mmax_bits[B_];     // per-b max of logits, encoded
__device__ int      g_sel[B_ * KSEL_];   // argmax indices
__device__ __align__(16) float g_Wf4[64 * D_ * 4];  // fused weight, packed [f4][d][4]
__device__ float    g_bias[D_];          // bk@W1[D:] + b1

// ---------------- f32x2 packed helpers (sm_103a) ----------------
__device__ __forceinline__ u64t pack2(float lo, float hi) {
    u64t r; asm("mov.b64 %0,{%1,%2};" : "=l"(r) : "f"(lo), "f"(hi)); return r;
}
__device__ __forceinline__ float2 unpack2(u64t v) {
    float2 r; asm("mov.b64 {%0,%1},%2;" : "=f"(r.x), "=f"(r.y) : "l"(v)); return r;
}
__device__ __forceinline__ u64t add2(u64t a, u64t b) {
    u64t r; asm("add.rn.f32x2 %0,%1,%2;" : "=l"(r) : "l"(a), "l"(b)); return r;
}
__device__ __forceinline__ u64t fma2(u64t a, u64t b, u64t c) {
    u64t r; asm("fma.rn.f32x2 %0,%1,%2,%3;" : "=l"(r) : "l"(a), "l"(b), "l"(c)); return r;
}
__device__ __forceinline__ u64t abs2(u64t a) { return a & 0x7FFFFFFF7FFFFFFFULL; }

__device__ __forceinline__ unsigned enc_f(float z) {
    unsigned u = __float_as_uint(z);
    return (u & 0x80000000u) ? ~u : (u | 0x80000000u);
}
__device__ __forceinline__ float dec_f(unsigned e) {
    unsigned u = (e & 0x80000000u) ? (e & 0x7fffffffu) : ~e;
    return __uint_as_float(u);
}

// ---------------- K1: fused prep -- Q/q_part (blocks 0..63), Wf (64..319), bias (320) ----
__global__ __launch_bounds__(128) void k_prep(const float* __restrict__ pe,
                                              const float* __restrict__ Wq,
                                              const float* __restrict__ bq,
                                              const float* __restrict__ Wk,
                                              const float* __restrict__ bk,
                                              const float* __restrict__ W1,
                                              const float* __restrict__ b1) {
    const int d = threadIdx.x;
    if (blockIdx.x < 64) {
        __shared__ float pes[F1_];
        __shared__ float Qs[D_];
        const int b = blockIdx.x;
        if (d == 0) g_mmax_bits[b] = 0u;       // reset per replay
        for (int i = d; i < F1_; i += 128) pes[i] = pe[b * F1_ + i];
        __syncthreads();
        float acc = bq[d];
        #pragma unroll 4
        for (int f = 0; f < F1_; f++) acc = fmaf(pes[f], Wq[f * D_ + d], acc);
        g_Q[b * D_ + d] = acc;
        Qs[d] = acc;
        __syncthreads();
        float a2 = 0.f;
        #pragma unroll 4
        for (int j = 0; j < D_; j++) a2 = fmaf(Qs[j], W1[j * D_ + d], a2);
        g_qp2f[d * B_ + b] = a2;
    } else {
        __shared__ float rowv[D_];
        const float* W1p = W1 + D_ * D_;
        if (blockIdx.x < 320) {
            const int f = blockIdx.x - 64;
            rowv[d] = Wk[f * D_ + d];
            __syncthreads();
            float acc = 0.f;
            #pragma unroll 4
            for (int j = 0; j < D_; j++) acc = fmaf(rowv[j], W1p[j * D_ + d], acc);
            g_Wf4[(((f >> 2) * D_) + d) * 4 + (f & 3)] = acc;   // packed [f4][d][4]
        } else {
            rowv[d] = bk[d];
            __syncthreads();
            float acc = b1[d];
            #pragma unroll 4
            for (int j = 0; j < D_; j++) acc = fmaf(rowv[j], W1p[j * D_ + d], acc);
            g_bias[d] = acc;
        }
    }
}

// ---------------- K2: kpbT = (ge @ Wf + bias)^T ----------------
__global__ __launch_bounds__(128) void k_gene(const float* __restrict__ ge) {
    __shared__ __align__(16) float ges[32][256];    // 32 KB, reused as transpose buffer
    const int d = threadIdx.x;
    const int n0 = blockIdx.x * 32;

    const float4* ge4 = (const float4*)(ge + n0 * F2_);
    for (int i = d; i < 32 * 64; i += 128) {
        int r = i >> 6, c = i & 63;
        *(float4*)&ges[r][c * 4] = ge4[r * 64 + c];
    }
    __syncthreads();

    float acc[32];
    const float bd = g_bias[d];
    #pragma unroll
    for (int r = 0; r < 32; r++) acc[r] = bd;

    const float4* Wf4 = (const float4*)g_Wf4;
    float4 wnext = Wf4[d];
    for (int f4 = 0; f4 < 64; f4++) {
        const float4 w = wnext;
        if (f4 < 63) wnext = Wf4[(f4 + 1) * D_ + d];
        const int f = f4 * 4;
        #pragma unroll
        for (int r = 0; r < 32; r++) {
            float4 x = *(const float4*)&ges[r][f];
            acc[r] = fmaf(x.x, w.x, acc[r]); acc[r] = fmaf(x.y, w.y, acc[r]);
            acc[r] = fmaf(x.z, w.z, acc[r]); acc[r] = fmaf(x.w, w.w, acc[r]);
        }
    }

    __syncthreads();                    // all reads of ges done
    float* st = (float*)ges;
    #pragma unroll
    for (int r = 0; r < 32; r++) st[d * 33 + r] = acc[r];
    __syncthreads();
    float* dst = g_kpbT + d * N_ + n0;
    #pragma unroll
    for (int j = 0; j < 8; j++) {
        float4 v;
        v.x = st[d * 33 + 4*j + 0]; v.y = st[d * 33 + 4*j + 1];
        v.z = st[d * 33 + 4*j + 2]; v.w = st[d * 33 + 4*j + 3];
        *(float4*)(dst + 4*j) = v;
    }
}

// ---------------- K3: logits m[b,n] -- 4 b x 4 n per thread, pipelined d-loop ----------------
// lrelu(x) = 0.55x + 0.45|x| -> w*lrelu(x) = (0.55w)x + (0.45w)|x|
__global__ __launch_bounds__(128) void k_logits(const float* __restrict__ w2,
                                                const float* __restrict__ b2p) {
    __shared__ u64t s_q2[D_][4];       // (q,q) duplicated pairs, [d][b_local]
    __shared__ u64t s_wa[D_], s_wb[D_];
    const int tid = threadIdx.x;
    const int lane = tid & 31;
    const int b0 = blockIdx.y * 4;

    for (int i = tid; i < 512; i += 128) {
        int d = i >> 2, j = i & 3;
        float q = g_qp2f[d * B_ + b0 + j];
        s_q2[d][j] = pack2(q, q);
    }
    {
        float w = w2[tid];
        s_wa[tid] = pack2(0.55f * w, 0.55f * w);
        s_wb[tid] = pack2(0.45f * w, 0.45f * w);
    }
    __syncthreads();

    const int n = (blockIdx.x * 128 + tid) * 4;
    const int nc = n <= N_ - 4 ? n : N_ - 4;
    const float* kT = g_kpbT + nc;

    u64t accA[4][2], accB[4][2];       // [b][n-pair]
    #pragma unroll
    for (int b = 0; b < 4; b++) { accA[b][0]=accA[b][1]=0ull; accB[b][0]=accB[b][1]=0ull; }

    // 4-deep prefetch pipeline over d
    float4 kc[4];
    #pragma unroll
    for (int i = 0; i < 4; i++) kc[i] = *(const float4*)(kT + i * N_);

    #pragma unroll 2
    for (int d0 = 0; d0 < D_ - 4; d0 += 4) {
        float4 cur[4];
        #pragma unroll
        for (int i = 0; i < 4; i++) cur[i] = kc[i];
        #pragma unroll
        for (int i = 0; i < 4; i++) kc[i] = *(const float4*)(kT + (d0 + 4 + i) * N_);
        #pragma unroll
        for (int i = 0; i < 4; i++) {
            const int d = d0 + i;
            u64t kn01 = pack2(cur[i].x, cur[i].y);
            u64t kn23 = pack2(cur[i].z, cur[i].w);
            u64t wa = s_wa[d], wb = s_wb[d];
            #pragma unroll
            for (int b = 0; b < 4; b++) {
                u64t q = s_q2[d][b];
                u64t x0 = add2(q, kn01);
                u64t x1 = add2(q, kn23);
                accA[b][0] = fma2(x0, wa, accA[b][0]);
                accB[b][0] = fma2(abs2(x0), wb, accB[b][0]);
                accA[b][1] = fma2(x1, wa, accA[b][1]);
                accB[b][1] = fma2(abs2(x1), wb, accB[b][1]);
            }
        }
    }
    // tail: d = 124..127 from kc
    #pragma unroll
    for (int i = 0; i < 4; i++) {
        const int d = D_ - 4 + i;
        u64t kn01 = pack2(kc[i].x, kc[i].y);
        u64t kn23 = pack2(kc[i].z, kc[i].w);
        u64t wa = s_wa[d], wb = s_wb[d];
        #pragma unroll
        for (int b = 0; b < 4; b++) {
            u64t q = s_q2[d][b];
            u64t x0 = add2(q, kn01);
            u64t x1 = add2(q, kn23);
            accA[b][0] = fma2(x0, wa, accA[b][0]);
            accB[b][0] = fma2(abs2(x0), wb, accB[b][0]);
            accA[b][1] = fma2(x1, wa, accA[b][1]);
            accB[b][1] = fma2(abs2(x1), wb, accB[b][1]);
        }
    }

    const float b2 = *b2p;
    float vals[4][4];                  // [b][n_local]
    #pragma unroll
    for (int b = 0; b < 4; b++) {
        float2 a01 = unpack2(add2(accA[b][0], accB[b][0]));
        float2 a23 = unpack2(add2(accA[b][1], accB[b][1]));
        vals[b][0] = (a01.x + b2) * 2.0f;   // /TEMP, TEMP=0.5
        vals[b][1] = (a01.y + b2) * 2.0f;
        vals[b][2] = (a23.x + b2) * 2.0f;
        vals[b][3] = (a23.y + b2) * 2.0f;
    }
    if (n <= N_ - 4) {
        #pragma unroll
        for (int b = 0; b < 4; b++) {
            float4 v; v.x = vals[b][0]; v.y = vals[b][1]; v.z = vals[b][2]; v.w = vals[b][3];
            *(float4*)(g_m + (b0 + b) * N_ + n) = v;
        }
    }
    #pragma unroll
    for (int b = 0; b < 4; b++) {
        float m = fmaxf(fmaxf(vals[b][0], vals[b][1]), fmaxf(vals[b][2], vals[b][3]));
        m = fmaxf(m, __shfl_xor_sync(0xffffffffu, m, 16));
        m = fmaxf(m, __shfl_xor_sync(0xffffffffu, m, 8));
        m = fmaxf(m, __shfl_xor_sync(0xffffffffu, m, 4));
        m = fmaxf(m, __shfl_xor_sync(0xffffffffu, m, 2));
        m = fmaxf(m, __shfl_xor_sync(0xffffffffu, m, 1));
        if (lane == 0) atomicMax(&g_mmax_bits[b0 + b], enc_f(m));
    }
}

// ---------------- K4: gumbel argmax (threefry2x32 partitionable) ----------------
__device__ __forceinline__ unsigned madu(unsigned a, unsigned one, unsigned c) {
    unsigned r; asm("mad.lo.s32 %0,%1,%2,%3;" : "=r"(r) : "r"(a), "r"(one), "r"(c)); return r;
}
// round-add AND key-injection adds via IMAD (fma pipe); SHF/LOP3 stay on alu pipe
#define TFRM(r) { x0 = madu(x1, one, x0); x1 = __funnelshift_l(x1, x1, (r)); x1 ^= x0; }

__device__ __forceinline__ unsigned threefry_bits(unsigned idx, unsigned one) {
    const unsigned ks1 = 42u, ks2 = 0x1BD11BF0u;   // ks0 = 0
    // round 1 with x0 == 0 simplified
    unsigned x1r = idx + ks1;
    unsigned x0 = x1r;
    unsigned x1 = __funnelshift_l(x1r, x1r, 13) ^ x0;
    TFRM(15) TFRM(26) TFRM(6);
    x0 = madu(ks1, one, x0);  x1 = madu(ks2 + 1u, one, x1);
    TFRM(17) TFRM(29) TFRM(16) TFRM(24);
    x0 = madu(ks2, one, x0);  x1 = madu(2u, one, x1);
    TFRM(13) TFRM(15) TFRM(26) TFRM(6);
    x1 = madu(ks1 + 3u, one, x1);   // x0 += 0
    TFRM(17) TFRM(29) TFRM(16) TFRM(24);
    x0 = madu(ks1, one, x0);  x1 = madu(ks2 + 4u, one, x1);
    TFRM(13) TFRM(15) TFRM(26) TFRM(6);
    x0 = madu(ks2, one, x0);  x1 = madu(5u, one, x1);
    return x0 ^ x1;
}

// candidate passes iff z might beat best. Integer form of "u > uth":
// u = mant * 2^-23 EXACTLY (mant = bits>>9), so u > uth  <=>  mant > trunc(uth*2^23).
// Truncation only weakens pruning (safe). s_uthm init -1: mant=0 passes until a best exists.
__device__ __forceinline__ void argmax_step(const float* __restrict__ mrow,
                                            float mmax, unsigned one,
                                            int n, unsigned idx,
                                            volatile int* s_uthm, int* s_uthm_nv,
                                            float& lbest, int& libest) {
    const int uthm = *s_uthm;
    unsigned bits = threefry_bits(idx, one);
    int mant = (int)(bits >> 9);
    if (mant > uthm) {
        float u = fmaxf(__uint_as_float((unsigned)mant | 0x3f800000u) - 1.0f,
                        1.17549435e-38f);
        float g = -logf(-logf(u));          // bit-matches XLA path
        float z = mrow[n] + g;
        if (z > lbest || (z == lbest && n < libest)) {
            lbest = z; libest = n;
            float nuth = expf(-expf(-(z - mmax))) - 2e-6f;
            if (nuth > 0.f) atomicMax(s_uthm_nv, (int)(nuth * 8388608.0f));
        }
    }
}

__global__ __launch_bounds__(256) void k_argmax() {
    const int row = blockIdx.x;            // b*KSEL + k
    const int b = row / KSEL_;
    const float* mrow = g_m + b * N_;
    const unsigned eb = g_mmax_bits[b];
    const float mmax = dec_f(eb);
    const unsigned one = (eb >> 31) | 1u;  // == 1 at runtime, opaque to ptxas
    __shared__ int s_uthm;                 // integer mantissa threshold
    __shared__ float szred[256];
    __shared__ int   sired[256];
    const int tid = threadIdx.x;
    if (tid == 0) s_uthm = -1;
    __syncthreads();

    const unsigned base = (unsigned)row * (unsigned)N_;
    float lbest = -1e30f;
    int   libest = 0x7fffffff;

    unsigned idx = base + (unsigned)tid;
    // 78 full iterations: n = j*256+tid <= 77*256+255 = 19967 < N_, no bound check
    for (int j = 0; j < 78; j++, idx += 256u) {
        argmax_step(mrow, mmax, one, j * 256 + tid, idx,
                    (volatile int*)&s_uthm, &s_uthm, lbest, libest);
    }
    // tail: n = 19968 + tid
    if (tid < N_ - 78 * 256) {
        argmax_step(mrow, mmax, one, 78 * 256 + tid, idx,
                    (volatile int*)&s_uthm, &s_uthm, lbest, libest);
    }
    szred[tid] = lbest; sired[tid] = libest;
    __syncthreads();
    for (int s = 128; s > 0; s >>= 1) {
        if (tid < s) {
            float oz = szred[tid + s]; int oi = sired[tid + s];
            if (oz > szred[tid] || (oz == szred[tid] && oi < sired[tid])) {
                szred[tid] = oz; sired[tid] = oi;
            }
        }
        __syncthreads();
    }
    if (tid == 0) g_sel[row] = sired[0];
}

// ---------------- K5: on-demand V rows + scores + softmax + context ----------------
__global__ __launch_bounds__(128) void k_context(const float* __restrict__ ge,
                                                 const float* __restrict__ Wv,
                                                 const float* __restrict__ bv,
                                                 float* __restrict__ out) {
    const int b = blockIdx.x, d = threadIdx.x;
    const int lane = d & 31, w = d >> 5;
    __shared__ int ssel[KSEL_];
    __shared__ __align__(16) float ges[KSEL_][256];
    __shared__ float part[4][KSEL_];
    __shared__ float ssc[KSEL_];
    if (d < KSEL_) ssel[d] = g_sel[b * KSEL_ + d];
    __syncthreads();
    for (int i = d; i < KSEL_ * 64; i += 128) {
        int k = i >> 6, c = i & 63;
        *(float4*)&ges[k][c * 4] = *(const float4*)(ge + ssel[k] * F2_ + c * 4);
    }
    __syncthreads();

    float v[KSEL_];
    const float bvd = bv[d];
    #pragma unroll
    for (int k = 0; k < KSEL_; k++) v[k] = bvd;
    for (int f = 0; f < F2_; f++) {
        const float wv = Wv[f * D_ + d];
        #pragma unroll
        for (int k = 0; k < KSEL_; k++) v[k] = fmaf(ges[k][f], wv, v[k]);
    }

    const float q = g_Q[b * D_ + d];
    #pragma unroll
    for (int k = 0; k < KSEL_; k++) {
        float p = q * v[k];
        p += __shfl_down_sync(0xffffffffu, p, 16);
        p += __shfl_down_sync(0xffffffffu, p, 8);
        p += __shfl_down_sync(0xffffffffu, p, 4);
        p += __shfl_down_sync(0xffffffffu, p, 2);
        p += __shfl_down_sync(0xffffffffu, p, 1);
        if (lane == 0) part[w][k] = p;
    }
    __syncthreads();
    if (d < KSEL_)
        ssc[d] = (part[0][d] + part[1][d] + part[2][d] + part[3][d]) / sqrtf(128.0f);
    __syncthreads();
    float mx = -1e30f;
    #pragma unroll
    for (int k = 0; k < KSEL_; k++) mx = fmaxf(mx, ssc[k]);
    float e[KSEL_], sum = 0.f;
    #pragma unroll
    for (int k = 0; k < KSEL_; k++) { e[k] = expf(ssc[k] - mx); sum += e[k]; }
    const float inv = 1.0f / sum;
    float ctx = 0.f;
    #pragma unroll
    for (int k = 0; k < KSEL_; k++) ctx = fmaf(e[k] * inv, v[k], ctx);
    out[b * D_ + d] = ctx;
}

// ---------------- launch ----------------
extern "C" void kernel_launch(void* const* d_in, const int* in_sizes, int n_in,
                              void* d_out, int out_size) {
    const float* pe = (const float*)d_in[0];
    const float* ge = (const float*)d_in[1];
    const float* Wq = (const float*)d_in[2];
    const float* bq = (const float*)d_in[3];
    const float* Wk = (const float*)d_in[4];
    const float* bk = (const float*)d_in[5];
    const float* Wv = (const float*)d_in[6];
    const float* bv = (const float*)d_in[7];
    const float* W1 = (const float*)d_in[8];
    const float* b1 = (const float*)d_in[9];
    const float* w2 = (const float*)d_in[10];
    const float* b2 = (const float*)d_in[11];

    k_prep<<<321, 128>>>(pe, Wq, bq, Wk, bk, W1, b1);
    k_gene<<<N_ / 32, 128>>>(ge);
    k_logits<<<dim3(40, 16), 128>>>(w2, b2);
    k_argmax<<<B_ * KSEL_, 256>>>();       // 4th launch -> profiled next round
    k_context<<<B_, 128>>>(ge, Wv, bv, (float*)d_out);
}